// round 13
// baseline (speedup 1.0000x reference)
#include <cuda_runtime.h>
#include <cuda_bf16.h>
#include <math_constants.h>
#include <cstdint>
#include <mma.h>

using namespace nvcuda;

#define NB     4
#define NSRC   2048
#define NDST   8192
#define CIN    256
#define CSKIP  128
#define CCAT   384
#define HDIM   256
#define COUT   128
#define PDIM   64
#define MTOT   (NB * NDST)          // 32768

#define OUT_ELEMS   (MTOT * COUT)   // 4194304
#define POS_ELEMS   (MTOT * 3)      // 98304

// ---------------------------------------------------------------------------
// Scratch (__device__ globals; no allocations allowed)
// ---------------------------------------------------------------------------
__device__ __nv_bfloat16 g_h1_hi[MTOT * HDIM];    // GEMM2 A hi plane
__device__ __nv_bfloat16 g_h1_lo[MTOT * HDIM];
__device__ __nv_bfloat16 g_w1t_hi[HDIM * CCAT];   // B1 [N=256, K=384]
__device__ __nv_bfloat16 g_w1t_lo[HDIM * CCAT];
__device__ __nv_bfloat16 g_w2t_hi[COUT * HDIM];   // B2 [N=128, K=256]
__device__ __nv_bfloat16 g_w2t_lo[COUT * HDIM];
__device__ float g_gate[NB * COUT];
__device__ int4   g_selI[MTOT];                   // j0, j1, j2, pad
__device__ float4 g_selW[MTOT];                   // w0, w1, w2, inv_den

// fp32 -> bf16 hi/lo split
__device__ __forceinline__ void split_bf16(float v, uint16_t& h, uint16_t& l) {
    __nv_bfloat16 hb = __float2bfloat16_rn(v);
    float r = v - __bfloat162float(hb);
    __nv_bfloat16 lb = __float2bfloat16_rn(r);
    h = __bfloat16_as_ushort(hb);
    l = __bfloat16_as_ushort(lb);
}

// cp.async helpers (sm_80 baseline — legal on sm_103 target)
__device__ __forceinline__ void cp_async16(uint32_t dst, const void* src) {
    asm volatile("cp.async.ca.shared.global [%0], [%1], 16;"
                 :: "r"(dst), "l"(src) : "memory");
}
#define CP_COMMIT() asm volatile("cp.async.commit_group;" ::: "memory")
#define CP_WAIT(n)  asm volatile("cp.async.wait_group %0;" :: "n"(n) : "memory")

// ---------------------------------------------------------------------------
// prep: gate + weight transpose/split + output tail (pos_skip, batch_skip)
// ---------------------------------------------------------------------------
__global__ void prep_kernel(const float* __restrict__ par,
                            const float* __restrict__ Wp,
                            const float* __restrict__ bp,
                            const float* __restrict__ W1,
                            const float* __restrict__ W2,
                            const float* __restrict__ pos_skip,
                            float* __restrict__ out, int mode, int out_size) {
    int i = blockIdx.x * 256 + threadIdx.x;
    if (i < NB * COUT) {
        int b = i >> 7, n = i & 127;
        float acc = bp[n];
        const float* pe = par + b * PDIM;
#pragma unroll
        for (int p = 0; p < PDIM; ++p)
            acc = fmaf(pe[p], Wp[p * COUT + n], acc);
        g_gate[i] = fmaxf(acc, 0.0f);
    }
    if (i < CCAT * HDIM) {
        int k = i / HDIM, n = i % HDIM;
        uint16_t h, l;
        split_bf16(W1[i], h, l);
        g_w1t_hi[n * CCAT + k] = __ushort_as_bfloat16(h);
        g_w1t_lo[n * CCAT + k] = __ushort_as_bfloat16(l);
    }
    if (i < HDIM * COUT) {
        int k = i / COUT, n = i % COUT;
        uint16_t h, l;
        split_bf16(W2[i], h, l);
        g_w2t_hi[n * HDIM + k] = __ushort_as_bfloat16(h);
        g_w2t_lo[n * HDIM + k] = __ushort_as_bfloat16(l);
    }
    // output tail
    if (i < POS_ELEMS && OUT_ELEMS + i < out_size)
        out[OUT_ELEMS + i] = pos_skip[i];
    if (i < MTOT) {
        if (mode == 1) {
            int o = OUT_ELEMS + POS_ELEMS + i;
            if (o < out_size) out[o] = (float)(i >> 13);
        } else if (mode == 2) {
            int o = OUT_ELEMS + POS_ELEMS + 2 * i;
            if (o + 1 < out_size)
                ((long long*)(out + OUT_ELEMS + POS_ELEMS))[i] = (long long)(i >> 13);
        }
    }
}

// ---------------------------------------------------------------------------
// KNN selection only (k=3). Thread-pair per point, even/odd candidate split,
// shfl merge with lowest-index tie-break == sequential-stable top_k.
// d2 rounding bit-matches the reference (R5-validated).
// ---------------------------------------------------------------------------
#define PTS_PER_BLK 128

__global__ __launch_bounds__(256)
void knn_select_kernel(const float* __restrict__ pos,
                       const float* __restrict__ pos_skip) {
    __shared__ float4 spos[NSRC];                 // (x, y, z, s2)  32 KB
    const int b   = blockIdx.y;
    const int tid = threadIdx.x;

    const float* sp = pos + (size_t)b * NSRC * 3;
    for (int i = tid; i < NSRC; i += 256) {
        float px = sp[i * 3 + 0];
        float py = sp[i * 3 + 1];
        float pz = sp[i * 3 + 2];
        float s2 = __fmaf_rn(pz, pz, __fmaf_rn(py, py, __fmul_rn(px, px)));
        spos[i] = make_float4(px, py, pz, s2);
    }
    __syncthreads();

    const int slot   = tid >> 1;
    const int parity = tid & 1;
    const int m  = b * NDST + blockIdx.x * PTS_PER_BLK + slot;
    const float dx = pos_skip[m * 3 + 0];
    const float dy = pos_skip[m * 3 + 1];
    const float dz = pos_skip[m * 3 + 2];
    const float dd = __fmaf_rn(dz, dz, __fmaf_rn(dy, dy, __fmul_rn(dx, dx)));

    float a0 = CUDART_INF_F, a1 = CUDART_INF_F, a2 = CUDART_INF_F;
    int   q0 = 0, q1 = 0, q2 = 0;

#pragma unroll 4
    for (int j = parity; j < NSRC; j += 2) {
        float4 c = spos[j];
        float d2 = __fadd_rn(__fadd_rn(dd, c.w),
                   -__fmul_rn(2.0f,
                    __fmaf_rn(dz, c.z, __fmaf_rn(dy, c.y, __fmul_rn(dx, c.x)))));
        bool p0 = d2 < a0, p1 = d2 < a1, p2 = d2 < a2;
        q2 = p1 ? q1 : (p2 ? j  : q2);
        a2 = p1 ? a1 : (p2 ? d2 : a2);
        q1 = p0 ? q0 : (p1 ? j  : q1);
        a1 = p0 ? a0 : (p1 ? d2 : a1);
        q0 = p0 ? j  : q0;
        a0 = p0 ? d2 : a0;
    }

    const unsigned FULL = 0xffffffffu;
    float oa0 = __shfl_down_sync(FULL, a0, 1);
    float oa1 = __shfl_down_sync(FULL, a1, 1);
    float oa2 = __shfl_down_sync(FULL, a2, 1);
    int   oq0 = __shfl_down_sync(FULL, q0, 1);
    int   oq1 = __shfl_down_sync(FULL, q1, 1);
    int   oq2 = __shfl_down_sync(FULL, q2, 1);

    if (parity == 0) {
#pragma unroll
        for (int t = 0; t < 3; ++t) {
            float d  = (t == 0) ? oa0 : (t == 1) ? oa1 : oa2;
            int   jj = (t == 0) ? oq0 : (t == 1) ? oq1 : oq2;
            bool lt0 = (d < a0) || (d == a0 && jj < q0);
            bool lt1 = (d < a1) || (d == a1 && jj < q1);
            bool lt2 = (d < a2) || (d == a2 && jj < q2);
            q2 = lt1 ? q1 : (lt2 ? jj : q2);
            a2 = lt1 ? a1 : (lt2 ? d  : a2);
            q1 = lt0 ? q0 : (lt1 ? jj : q1);
            a1 = lt0 ? a0 : (lt1 ? d  : a1);
            q0 = lt0 ? jj : q0;
            a0 = lt0 ? d  : a0;
        }
        float w0 = __fdiv_rn(1.0f, fmaxf(a0, 1e-16f));
        float w1 = __fdiv_rn(1.0f, fmaxf(a1, 1e-16f));
        float w2 = __fdiv_rn(1.0f, fmaxf(a2, 1e-16f));
        float den = __fadd_rn(__fadd_rn(w0, w1), w2);
        g_selI[m] = make_int4(q0, q1, q2, 0);
        g_selW[m] = make_float4(w0, w1, w2, __fdiv_rn(1.0f, den));
    }
}

// ---------------------------------------------------------------------------
// Shared GEMM tile constants
// ---------------------------------------------------------------------------
#define BK_G   32
#define STRD   40                          // 80B row stride: conflict-free LDSM
#define PL_B   (128 * STRD * 2)            // plane bytes = 10240
#define BUF_B  (4 * PL_B)                  // 4 planes per buffer = 40960
#define CSTR   68                          // epilogue C buffer stride (floats)

// ---------------------------------------------------------------------------
// GEMM1 fused:  h1 = relu( interp_concat(x, x_skip) @ W1 + b1 )
//   stageA is WARP-COOPERATIVE: half-warp = one A row; lane pairs load
//   float2 at consecutive cols -> each source-row read = one coalesced
//   128B transaction (vs 32-line scatter in R12). Selections preloaded
//   into static smem. Interp arithmetic identical to R12 (bit-exact).
// ---------------------------------------------------------------------------
__global__ __launch_bounds__(256, 2)
void gemm1_fused_kernel(const float* __restrict__ x,
                        const float* __restrict__ x_skip,
                        const __nv_bfloat16* __restrict__ Bh,
                        const __nv_bfloat16* __restrict__ Bl,
                        const float* __restrict__ bias) {
    constexpr int NC = CCAT / BK_G;        // 12
    extern __shared__ char smem[];
    __shared__ int4   ssel[128];
    __shared__ float4 swgt[128];
    const uint32_t sbase = (uint32_t)__cvta_generic_to_shared(smem);

    const int tid  = threadIdx.x;
    const int w    = tid >> 5;
    const int lane = tid & 31;
    const int bm   = blockIdx.y * 128;
    const int bn   = blockIdx.x * 128;
    const int wm   = (w & 3) * 32;
    const int wn   = (w >> 2) * 64;
    const int batch = bm >> 13;
    const size_t xbase = (size_t)batch * NSRC;

    // preload selections for this M-tile
    if (tid < 128) {
        ssel[tid] = g_selI[bm + tid];
        swgt[tid] = g_selW[bm + tid];
    }
    __syncthreads();

    const int half = lane >> 4;            // 0/1: which of 2 rows this iter
    const int c2   = lane & 15;            // column pair index (2 cols each)

    auto stageA = [&](int kc, int buf) {
        char* base = smem + buf * BUF_B;
        if (kc < CIN / BK_G) {             // interp region, 8 chunks
            const int col0 = kc * BK_G + c2 * 2;
#pragma unroll
            for (int it = 0; it < 8; ++it) {
                const int row = w * 16 + it * 2 + half;
                const int4   si = ssel[row];
                const float4 sw = swgt[row];
                float2 r0 = *(const float2*)(x + (xbase + si.x) * CIN + col0);
                float2 r1 = *(const float2*)(x + (xbase + si.y) * CIN + col0);
                float2 r2 = *(const float2*)(x + (xbase + si.z) * CIN + col0);
                float v0 = __fmul_rn(__fadd_rn(__fadd_rn(__fmul_rn(sw.x, r0.x),
                                                         __fmul_rn(sw.y, r1.x)),
                                               __fmul_rn(sw.z, r2.x)), sw.w);
                float v1 = __fmul_rn(__fadd_rn(__fadd_rn(__fmul_rn(sw.x, r0.y),
                                                         __fmul_rn(sw.y, r1.y)),
                                               __fmul_rn(sw.z, r2.y)), sw.w);
                uint16_t h0, l0, h1, l1;
                split_bf16(v0, h0, l0);
                split_bf16(v1, h1, l1);
                *(uint32_t*)(base + row * (STRD * 2) + c2 * 4) =
                    (uint32_t)h0 | ((uint32_t)h1 << 16);
                *(uint32_t*)(base + PL_B + row * (STRD * 2) + c2 * 4) =
                    (uint32_t)l0 | ((uint32_t)l1 << 16);
            }
        } else {                           // x_skip region, 4 chunks
            const int col0 = kc * BK_G - CIN + c2 * 2;
#pragma unroll
            for (int it = 0; it < 8; ++it) {
                const int row = w * 16 + it * 2 + half;
                float2 s = *(const float2*)(x_skip + (size_t)(bm + row) * CSKIP + col0);
                uint16_t h0, l0, h1, l1;
                split_bf16(s.x, h0, l0);
                split_bf16(s.y, h1, l1);
                *(uint32_t*)(base + row * (STRD * 2) + c2 * 4) =
                    (uint32_t)h0 | ((uint32_t)h1 << 16);
                *(uint32_t*)(base + PL_B + row * (STRD * 2) + c2 * 4) =
                    (uint32_t)l0 | ((uint32_t)l1 << 16);
            }
        }
    };

    auto stageB = [&](int kc, int buf) {
#pragma unroll
        for (int u = tid; u < 1024; u += 256) {
            const int plane = u >> 9;
            const int idx   = u & 511;
            const int row   = idx >> 2;
            const int c     = idx & 3;
            const __nv_bfloat16* P = plane ? Bl : Bh;
            const __nv_bfloat16* gsrc =
                P + (size_t)(bn + row) * CCAT + kc * BK_G + c * 8;
            uint32_t sdst = sbase + buf * BUF_B + (2 + plane) * PL_B +
                            row * (STRD * 2) + c * 16;
            cp_async16(sdst, gsrc);
        }
    };

    wmma::fragment<wmma::accumulator, 16, 16, 16, float> acc[2][4];
#pragma unroll
    for (int i = 0; i < 2; ++i)
#pragma unroll
        for (int j = 0; j < 4; ++j)
            wmma::fill_fragment(acc[i][j], 0.0f);

    stageB(0, 0);
    CP_COMMIT();
    stageA(0, 0);
    CP_WAIT(0);
    __syncthreads();

    for (int kc = 0; kc < NC; ++kc) {
        if (kc + 1 < NC) {
            stageB(kc + 1, (kc + 1) & 1);
            CP_COMMIT();
            stageA(kc + 1, (kc + 1) & 1);
        }

        const __nv_bfloat16* sb =
            (const __nv_bfloat16*)(smem + (kc & 1) * BUF_B);
        const __nv_bfloat16* sAh = sb;
        const __nv_bfloat16* sAl = sb + 128 * STRD;
        const __nv_bfloat16* sBh = sb + 2 * 128 * STRD;
        const __nv_bfloat16* sBl = sb + 3 * 128 * STRD;

#pragma unroll
        for (int kk = 0; kk < BK_G; kk += 16) {
            wmma::fragment<wmma::matrix_a, 16, 16, 16, __nv_bfloat16,
                           wmma::row_major> a_h[2], a_l[2];
#pragma unroll
            for (int i = 0; i < 2; ++i) {
                wmma::load_matrix_sync(a_h[i], sAh + (wm + i * 16) * STRD + kk, STRD);
                wmma::load_matrix_sync(a_l[i], sAl + (wm + i * 16) * STRD + kk, STRD);
            }
#pragma unroll
            for (int j = 0; j < 4; ++j) {
                wmma::fragment<wmma::matrix_b, 16, 16, 16, __nv_bfloat16,
                               wmma::col_major> b_h, b_l;
                wmma::load_matrix_sync(b_h, sBh + (wn + j * 16) * STRD + kk, STRD);
                wmma::load_matrix_sync(b_l, sBl + (wn + j * 16) * STRD + kk, STRD);
                wmma::mma_sync(acc[0][j], a_h[0], b_h, acc[0][j]);
                wmma::mma_sync(acc[1][j], a_h[1], b_h, acc[1][j]);
                wmma::mma_sync(acc[0][j], a_h[0], b_l, acc[0][j]);
                wmma::mma_sync(acc[1][j], a_h[1], b_l, acc[1][j]);
                wmma::mma_sync(acc[0][j], a_l[0], b_h, acc[0][j]);
                wmma::mma_sync(acc[1][j], a_l[1], b_h, acc[1][j]);
            }
        }
        if (kc + 1 < NC) CP_WAIT(0);
        __syncthreads();
    }

    // epilogue: bias + relu + split -> g_h1 planes
    float* cw = (float*)smem + w * (32 * CSTR);
#pragma unroll
    for (int i = 0; i < 2; ++i)
#pragma unroll
        for (int j = 0; j < 4; ++j)
            wmma::store_matrix_sync(cw + i * 16 * CSTR + j * 16, acc[i][j],
                                    CSTR, wmma::mem_row_major);
    __syncwarp();

    const int m = bm + wm + lane;
    const int ncol0 = bn + wn;
    uint32_t* dh = (uint32_t*)(g_h1_hi + (size_t)m * HDIM + ncol0);
    uint32_t* dl = (uint32_t*)(g_h1_lo + (size_t)m * HDIM + ncol0);
#pragma unroll
    for (int c = 0; c < 64; c += 2) {
        float v0 = fmaxf(cw[lane * CSTR + c]     + bias[ncol0 + c],     0.0f);
        float v1 = fmaxf(cw[lane * CSTR + c + 1] + bias[ncol0 + c + 1], 0.0f);
        uint16_t h0, l0, h1, l1;
        split_bf16(v0, h0, l0);
        split_bf16(v1, h1, l1);
        dh[c >> 1] = (uint32_t)h0 | ((uint32_t)h1 << 16);
        dl[c >> 1] = (uint32_t)l0 | ((uint32_t)l1 << 16);
    }
}

// ---------------------------------------------------------------------------
// GEMM2 (unchanged): out = (h1 @ W2 + b2) * gate[batch]
// ---------------------------------------------------------------------------
__global__ __launch_bounds__(256, 2)
void gemm2_kernel(const __nv_bfloat16* __restrict__ Ah,
                  const __nv_bfloat16* __restrict__ Al,
                  const __nv_bfloat16* __restrict__ Bh,
                  const __nv_bfloat16* __restrict__ Bl,
                  const float* __restrict__ bias,
                  float* __restrict__ outp) {
    constexpr int KTOT = HDIM;
    constexpr int N    = COUT;
    constexpr int NC   = KTOT / BK_G;      // 8
    extern __shared__ char smem[];
    const uint32_t sbase = (uint32_t)__cvta_generic_to_shared(smem);

    const int tid  = threadIdx.x;
    const int w    = tid >> 5;
    const int lane = tid & 31;
    const int bm   = blockIdx.y * 128;
    const int bn   = blockIdx.x * 128;
    const int wm   = (w & 3) * 32;
    const int wn   = (w >> 2) * 64;

    auto stage = [&](int kc, int buf) {
#pragma unroll
        for (int u = tid; u < 2048; u += 256) {
            const int plane = u >> 9;
            const int idx   = u & 511;
            const int row   = idx >> 2;
            const int c     = idx & 3;
            const __nv_bfloat16* P =
                (plane == 0) ? Ah : (plane == 1) ? Al : (plane == 2) ? Bh : Bl;
            const int grow = (plane < 2) ? (bm + row) : (bn + row);
            const __nv_bfloat16* gsrc =
                P + (size_t)grow * KTOT + kc * BK_G + c * 8;
            uint32_t sdst = sbase + buf * BUF_B + plane * PL_B +
                            row * (STRD * 2) + c * 16;
            cp_async16(sdst, gsrc);
        }
    };

    wmma::fragment<wmma::accumulator, 16, 16, 16, float> acc[2][4];
#pragma unroll
    for (int i = 0; i < 2; ++i)
#pragma unroll
        for (int j = 0; j < 4; ++j)
            wmma::fill_fragment(acc[i][j], 0.0f);

    stage(0, 0);
    CP_COMMIT();

    for (int kc = 0; kc < NC; ++kc) {
        if (kc + 1 < NC) {
            stage(kc + 1, (kc + 1) & 1);
            CP_COMMIT();
            CP_WAIT(1);
        } else {
            CP_WAIT(0);
        }
        __syncthreads();

        const __nv_bfloat16* sb =
            (const __nv_bfloat16*)(smem + (kc & 1) * BUF_B);
        const __nv_bfloat16* sAh = sb;
        const __nv_bfloat16* sAl = sb + 128 * STRD;
        const __nv_bfloat16* sBh = sb + 2 * 128 * STRD;
        const __nv_bfloat16* sBl = sb + 3 * 128 * STRD;

#pragma unroll
        for (int kk = 0; kk < BK_G; kk += 16) {
            wmma::fragment<wmma::matrix_a, 16, 16, 16, __nv_bfloat16,
                           wmma::row_major> a_h[2], a_l[2];
#pragma unroll
            for (int i = 0; i < 2; ++i) {
                wmma::load_matrix_sync(a_h[i], sAh + (wm + i * 16) * STRD + kk, STRD);
                wmma::load_matrix_sync(a_l[i], sAl + (wm + i * 16) * STRD + kk, STRD);
            }
#pragma unroll
            for (int j = 0; j < 4; ++j) {
                wmma::fragment<wmma::matrix_b, 16, 16, 16, __nv_bfloat16,
                               wmma::col_major> b_h, b_l;
                wmma::load_matrix_sync(b_h, sBh + (wn + j * 16) * STRD + kk, STRD);
                wmma::load_matrix_sync(b_l, sBl + (wn + j * 16) * STRD + kk, STRD);
                wmma::mma_sync(acc[0][j], a_h[0], b_h, acc[0][j]);
                wmma::mma_sync(acc[1][j], a_h[1], b_h, acc[1][j]);
                wmma::mma_sync(acc[0][j], a_h[0], b_l, acc[0][j]);
                wmma::mma_sync(acc[1][j], a_h[1], b_l, acc[1][j]);
                wmma::mma_sync(acc[0][j], a_l[0], b_h, acc[0][j]);
                wmma::mma_sync(acc[1][j], a_l[1], b_h, acc[1][j]);
            }
        }
        __syncthreads();
    }

    float* cw = (float*)smem + w * (32 * CSTR);
#pragma unroll
    for (int i = 0; i < 2; ++i)
#pragma unroll
        for (int j = 0; j < 4; ++j)
            wmma::store_matrix_sync(cw + i * 16 * CSTR + j * 16, acc[i][j],
                                    CSTR, wmma::mem_row_major);
    __syncwarp();

    const int m = bm + wm + lane;
    const int ncol0 = bn + wn;
    const int batch = m >> 13;
    const float* gt = g_gate + batch * COUT;
    float4* dst = (float4*)(outp + (size_t)m * N + ncol0);
#pragma unroll
    for (int c = 0; c < 64; c += 4) {
        float4 o;
        o.x = (cw[lane * CSTR + c]     + bias[ncol0 + c])     * gt[ncol0 + c];
        o.y = (cw[lane * CSTR + c + 1] + bias[ncol0 + c + 1]) * gt[ncol0 + c + 1];
        o.z = (cw[lane * CSTR + c + 2] + bias[ncol0 + c + 2]) * gt[ncol0 + c + 2];
        o.w = (cw[lane * CSTR + c + 3] + bias[ncol0 + c + 3]) * gt[ncol0 + c + 3];
        dst[c >> 2] = o;
    }
}

// ---------------------------------------------------------------------------
extern "C" void kernel_launch(void* const* d_in, const int* in_sizes, int n_in,
                              void* d_out, int out_size) {
    const float* par      = (const float*)d_in[0];
    const float* x        = (const float*)d_in[1];
    const float* pos      = (const float*)d_in[2];
    const float* x_skip   = (const float*)d_in[3];
    const float* pos_skip = (const float*)d_in[4];
    const float* W1       = (const float*)d_in[5];
    const float* b1       = (const float*)d_in[6];
    const float* W2       = (const float*)d_in[7];
    const float* b2       = (const float*)d_in[8];
    const float* Wp       = (const float*)d_in[9];
    const float* bp       = (const float*)d_in[10];
    float* out = (float*)d_out;

    __nv_bfloat16 *p_hh, *p_hl, *p_w1h, *p_w1l, *p_w2h, *p_w2l;
    cudaGetSymbolAddress((void**)&p_hh,  g_h1_hi);
    cudaGetSymbolAddress((void**)&p_hl,  g_h1_lo);
    cudaGetSymbolAddress((void**)&p_w1h, g_w1t_hi);
    cudaGetSymbolAddress((void**)&p_w1l, g_w1t_lo);
    cudaGetSymbolAddress((void**)&p_w2h, g_w2t_hi);
    cudaGetSymbolAddress((void**)&p_w2l, g_w2t_lo);

    constexpr int SMEM_G = 2 * BUF_B;   // 81920
    cudaFuncSetAttribute(gemm1_fused_kernel,
                         cudaFuncAttributeMaxDynamicSharedMemorySize, SMEM_G);
    cudaFuncSetAttribute(gemm2_kernel,
                         cudaFuncAttributeMaxDynamicSharedMemorySize, SMEM_G);

    const int tail = out_size - OUT_ELEMS;
    int mode = 0;
    if (tail >= POS_ELEMS + 2 * MTOT)      mode = 2;
    else if (tail >= POS_ELEMS + MTOT)     mode = 1;

    prep_kernel<<<(POS_ELEMS + 255) / 256, 256>>>(par, Wp, bp, W1, W2,
                                                  pos_skip, out, mode, out_size);

    dim3 kg(NDST / PTS_PER_BLK, NB);       // (64, 4)
    knn_select_kernel<<<kg, 256>>>(pos, pos_skip);

    dim3 g1(HDIM / 128, MTOT / 128);       // (2, 256)
    gemm1_fused_kernel<<<g1, 256, SMEM_G>>>(x, x_skip, p_w1h, p_w1l, b1);

    dim3 g2(COUT / 128, MTOT / 128);       // (1, 256)
    gemm2_kernel<<<g2, 256, SMEM_G>>>(p_hh, p_hl, p_w2h, p_w2l, b2, out);
}

// round 14
// speedup vs baseline: 1.3760x; 1.3760x over previous
#include <cuda_runtime.h>
#include <cuda_bf16.h>
#include <math_constants.h>
#include <cstdint>
#include <mma.h>

using namespace nvcuda;

#define NB     4
#define NSRC   2048
#define NDST   8192
#define CIN    256
#define CSKIP  128
#define CCAT   384
#define HDIM   256
#define COUT   128
#define PDIM   64
#define MTOT   (NB * NDST)          // 32768
#define MSRC   (NB * NSRC)          // 8192

#define OUT_ELEMS   (MTOT * COUT)   // 4194304
#define POS_ELEMS   (MTOT * 3)      // 98304

// ---------------------------------------------------------------------------
// Scratch (__device__ globals; no allocations allowed)
// ---------------------------------------------------------------------------
__device__ float         g_Z[MSRC * HDIM];        // x @ W1_top, fp32 (8 MB)
__device__ __nv_bfloat16 g_h1_hi[MTOT * HDIM];    // GEMM2 A hi plane
__device__ __nv_bfloat16 g_h1_lo[MTOT * HDIM];
__device__ __nv_bfloat16 g_w1t_hi[HDIM * CCAT];   // W1^T planes [N=256, K=384]
__device__ __nv_bfloat16 g_w1t_lo[HDIM * CCAT];
__device__ __nv_bfloat16 g_w2t_hi[COUT * HDIM];   // W2^T planes [N=128, K=256]
__device__ __nv_bfloat16 g_w2t_lo[COUT * HDIM];
__device__ float g_gate[NB * COUT];
__device__ int4   g_selI[MTOT];                   // j0, j1, j2, pad
__device__ float4 g_selW[MTOT];                   // w0, w1, w2, inv_den

// fp32 -> bf16 hi/lo split
__device__ __forceinline__ void split_bf16(float v, uint16_t& h, uint16_t& l) {
    __nv_bfloat16 hb = __float2bfloat16_rn(v);
    float r = v - __bfloat162float(hb);
    __nv_bfloat16 lb = __float2bfloat16_rn(r);
    h = __bfloat16_as_ushort(hb);
    l = __bfloat16_as_ushort(lb);
}

// cp.async helpers (sm_80 baseline — legal on sm_103 target)
__device__ __forceinline__ void cp_async16(uint32_t dst, const void* src) {
    asm volatile("cp.async.ca.shared.global [%0], [%1], 16;"
                 :: "r"(dst), "l"(src) : "memory");
}
#define CP_COMMIT() asm volatile("cp.async.commit_group;" ::: "memory")
#define CP_WAIT(n)  asm volatile("cp.async.wait_group %0;" :: "n"(n) : "memory")

// ---------------------------------------------------------------------------
// prep: gate + weight transpose/split + output tail (pos_skip, batch_skip)
// ---------------------------------------------------------------------------
__global__ void prep_kernel(const float* __restrict__ par,
                            const float* __restrict__ Wp,
                            const float* __restrict__ bp,
                            const float* __restrict__ W1,
                            const float* __restrict__ W2,
                            const float* __restrict__ pos_skip,
                            float* __restrict__ out, int mode, int out_size) {
    int i = blockIdx.x * 256 + threadIdx.x;
    if (i < NB * COUT) {
        int b = i >> 7, n = i & 127;
        float acc = bp[n];
        const float* pe = par + b * PDIM;
#pragma unroll
        for (int p = 0; p < PDIM; ++p)
            acc = fmaf(pe[p], Wp[p * COUT + n], acc);
        g_gate[i] = fmaxf(acc, 0.0f);
    }
    if (i < CCAT * HDIM) {
        int k = i / HDIM, n = i % HDIM;
        uint16_t h, l;
        split_bf16(W1[i], h, l);
        g_w1t_hi[n * CCAT + k] = __ushort_as_bfloat16(h);
        g_w1t_lo[n * CCAT + k] = __ushort_as_bfloat16(l);
    }
    if (i < HDIM * COUT) {
        int k = i / COUT, n = i % COUT;
        uint16_t h, l;
        split_bf16(W2[i], h, l);
        g_w2t_hi[n * HDIM + k] = __ushort_as_bfloat16(h);
        g_w2t_lo[n * HDIM + k] = __ushort_as_bfloat16(l);
    }
    // output tail
    if (i < POS_ELEMS && OUT_ELEMS + i < out_size)
        out[OUT_ELEMS + i] = pos_skip[i];
    if (i < MTOT) {
        if (mode == 1) {
            int o = OUT_ELEMS + POS_ELEMS + i;
            if (o < out_size) out[o] = (float)(i >> 13);
        } else if (mode == 2) {
            int o = OUT_ELEMS + POS_ELEMS + 2 * i;
            if (o + 1 < out_size)
                ((long long*)(out + OUT_ELEMS + POS_ELEMS))[i] = (long long)(i >> 13);
        }
    }
}

// ---------------------------------------------------------------------------
// KNN selection only (k=3). Thread-pair per point, even/odd candidate split,
// shfl merge with lowest-index tie-break == sequential-stable top_k.
// d2 rounding bit-matches the reference (R5-validated).
// ---------------------------------------------------------------------------
#define PTS_PER_BLK 128

__global__ __launch_bounds__(256)
void knn_select_kernel(const float* __restrict__ pos,
                       const float* __restrict__ pos_skip) {
    __shared__ float4 spos[NSRC];                 // (x, y, z, s2)  32 KB
    const int b   = blockIdx.y;
    const int tid = threadIdx.x;

    const float* sp = pos + (size_t)b * NSRC * 3;
    for (int i = tid; i < NSRC; i += 256) {
        float px = sp[i * 3 + 0];
        float py = sp[i * 3 + 1];
        float pz = sp[i * 3 + 2];
        float s2 = __fmaf_rn(pz, pz, __fmaf_rn(py, py, __fmul_rn(px, px)));
        spos[i] = make_float4(px, py, pz, s2);
    }
    __syncthreads();

    const int slot   = tid >> 1;
    const int parity = tid & 1;
    const int m  = b * NDST + blockIdx.x * PTS_PER_BLK + slot;
    const float dx = pos_skip[m * 3 + 0];
    const float dy = pos_skip[m * 3 + 1];
    const float dz = pos_skip[m * 3 + 2];
    const float dd = __fmaf_rn(dz, dz, __fmaf_rn(dy, dy, __fmul_rn(dx, dx)));

    float a0 = CUDART_INF_F, a1 = CUDART_INF_F, a2 = CUDART_INF_F;
    int   q0 = 0, q1 = 0, q2 = 0;

#pragma unroll 4
    for (int j = parity; j < NSRC; j += 2) {
        float4 c = spos[j];
        float d2 = __fadd_rn(__fadd_rn(dd, c.w),
                   -__fmul_rn(2.0f,
                    __fmaf_rn(dz, c.z, __fmaf_rn(dy, c.y, __fmul_rn(dx, c.x)))));
        bool p0 = d2 < a0, p1 = d2 < a1, p2 = d2 < a2;
        q2 = p1 ? q1 : (p2 ? j  : q2);
        a2 = p1 ? a1 : (p2 ? d2 : a2);
        q1 = p0 ? q0 : (p1 ? j  : q1);
        a1 = p0 ? a0 : (p1 ? d2 : a1);
        q0 = p0 ? j  : q0;
        a0 = p0 ? d2 : a0;
    }

    const unsigned FULL = 0xffffffffu;
    float oa0 = __shfl_down_sync(FULL, a0, 1);
    float oa1 = __shfl_down_sync(FULL, a1, 1);
    float oa2 = __shfl_down_sync(FULL, a2, 1);
    int   oq0 = __shfl_down_sync(FULL, q0, 1);
    int   oq1 = __shfl_down_sync(FULL, q1, 1);
    int   oq2 = __shfl_down_sync(FULL, q2, 1);

    if (parity == 0) {
#pragma unroll
        for (int t = 0; t < 3; ++t) {
            float d  = (t == 0) ? oa0 : (t == 1) ? oa1 : oa2;
            int   jj = (t == 0) ? oq0 : (t == 1) ? oq1 : oq2;
            bool lt0 = (d < a0) || (d == a0 && jj < q0);
            bool lt1 = (d < a1) || (d == a1 && jj < q1);
            bool lt2 = (d < a2) || (d == a2 && jj < q2);
            q2 = lt1 ? q1 : (lt2 ? jj : q2);
            a2 = lt1 ? a1 : (lt2 ? d  : a2);
            q1 = lt0 ? q0 : (lt1 ? jj : q1);
            a1 = lt0 ? a0 : (lt1 ? d  : a1);
            q0 = lt0 ? jj : q0;
            a0 = lt0 ? d  : a0;
        }
        float w0 = __fdiv_rn(1.0f, fmaxf(a0, 1e-16f));
        float w1 = __fdiv_rn(1.0f, fmaxf(a1, 1e-16f));
        float w2 = __fdiv_rn(1.0f, fmaxf(a2, 1e-16f));
        float den = __fadd_rn(__fadd_rn(w0, w1), w2);
        g_selI[m] = make_int4(q0, q1, q2, 0);
        g_selW[m] = make_float4(w0, w1, w2, __fdiv_rn(1.0f, den));
    }
}

// ---------------------------------------------------------------------------
// Shared GEMM tile constants
// ---------------------------------------------------------------------------
#define BK_G   32
#define STRD   40                          // 80B row stride: conflict-free LDSM
#define PL_B   (128 * STRD * 2)            // plane bytes = 10240
#define BUF_B  (4 * PL_B)                  // 4 planes per buffer = 40960
#define CSTR   68                          // epilogue C buffer stride (floats)

// ---------------------------------------------------------------------------
// Core split-bf16 MMA mainloop (A fp32 staged+split on the fly, B planes).
// AK    = A row stride (fp32 elems);  BK_STRIDE = B plane row stride (bf16)
// BOFF  = column offset into B planes
// ---------------------------------------------------------------------------
template<int NC, int AK, int BSTRIDE, int BOFF>
__device__ __forceinline__ void mma_mainloop_f32A(
    const float* __restrict__ A, int bm,
    const __nv_bfloat16* __restrict__ Bh,
    const __nv_bfloat16* __restrict__ Bl, int bn,
    char* smem, uint32_t sbase, int tid, int wm, int wn,
    wmma::fragment<wmma::accumulator, 16, 16, 16, float> (&acc)[2][4]) {

    const int arow = tid >> 1;
    const int aseg = tid & 1;

    auto stageA = [&](int kc, int buf) {
        const float* src = A + (size_t)(bm + arow) * AK + kc * BK_G + aseg * 16;
        float v[16];
#pragma unroll
        for (int q = 0; q < 4; ++q) {
            float4 s = *(const float4*)(src + q * 4);
            v[q * 4 + 0] = s.x; v[q * 4 + 1] = s.y;
            v[q * 4 + 2] = s.z; v[q * 4 + 3] = s.w;
        }
        uint32_t hp[8], lp[8];
#pragma unroll
        for (int e = 0; e < 16; e += 2) {
            uint16_t h0, l0, h1, l1;
            split_bf16(v[e],     h0, l0);
            split_bf16(v[e + 1], h1, l1);
            hp[e >> 1] = (uint32_t)h0 | ((uint32_t)h1 << 16);
            lp[e >> 1] = (uint32_t)l0 | ((uint32_t)l1 << 16);
        }
        char* base = smem + buf * BUF_B;
        uint4* dh = (uint4*)(base + arow * (STRD * 2) + aseg * 32);
        uint4* dl = (uint4*)(base + PL_B + arow * (STRD * 2) + aseg * 32);
        dh[0] = make_uint4(hp[0], hp[1], hp[2], hp[3]);
        dh[1] = make_uint4(hp[4], hp[5], hp[6], hp[7]);
        dl[0] = make_uint4(lp[0], lp[1], lp[2], lp[3]);
        dl[1] = make_uint4(lp[4], lp[5], lp[6], lp[7]);
    };

    auto stageB = [&](int kc, int buf) {
#pragma unroll
        for (int u = tid; u < 1024; u += 256) {
            const int plane = u >> 9;
            const int idx   = u & 511;
            const int row   = idx >> 2;
            const int c     = idx & 3;
            const __nv_bfloat16* P = plane ? Bl : Bh;
            const __nv_bfloat16* gsrc =
                P + (size_t)(bn + row) * BSTRIDE + BOFF + kc * BK_G + c * 8;
            uint32_t sdst = sbase + buf * BUF_B + (2 + plane) * PL_B +
                            row * (STRD * 2) + c * 16;
            cp_async16(sdst, gsrc);
        }
    };

    stageB(0, 0);
    CP_COMMIT();
    stageA(0, 0);
    CP_WAIT(0);
    __syncthreads();

    for (int kc = 0; kc < NC; ++kc) {
        if (kc + 1 < NC) {
            stageB(kc + 1, (kc + 1) & 1);
            CP_COMMIT();
            stageA(kc + 1, (kc + 1) & 1);
        }

        const __nv_bfloat16* sb =
            (const __nv_bfloat16*)(smem + (kc & 1) * BUF_B);
        const __nv_bfloat16* sAh = sb;
        const __nv_bfloat16* sAl = sb + 128 * STRD;
        const __nv_bfloat16* sBh = sb + 2 * 128 * STRD;
        const __nv_bfloat16* sBl = sb + 3 * 128 * STRD;

#pragma unroll
        for (int kk = 0; kk < BK_G; kk += 16) {
            wmma::fragment<wmma::matrix_a, 16, 16, 16, __nv_bfloat16,
                           wmma::row_major> a_h[2], a_l[2];
#pragma unroll
            for (int i = 0; i < 2; ++i) {
                wmma::load_matrix_sync(a_h[i], sAh + (wm + i * 16) * STRD + kk, STRD);
                wmma::load_matrix_sync(a_l[i], sAl + (wm + i * 16) * STRD + kk, STRD);
            }
#pragma unroll
            for (int j = 0; j < 4; ++j) {
                wmma::fragment<wmma::matrix_b, 16, 16, 16, __nv_bfloat16,
                               wmma::col_major> b_h, b_l;
                wmma::load_matrix_sync(b_h, sBh + (wn + j * 16) * STRD + kk, STRD);
                wmma::load_matrix_sync(b_l, sBl + (wn + j * 16) * STRD + kk, STRD);
                wmma::mma_sync(acc[0][j], a_h[0], b_h, acc[0][j]);
                wmma::mma_sync(acc[1][j], a_h[1], b_h, acc[1][j]);
                wmma::mma_sync(acc[0][j], a_h[0], b_l, acc[0][j]);
                wmma::mma_sync(acc[1][j], a_h[1], b_l, acc[1][j]);
                wmma::mma_sync(acc[0][j], a_l[0], b_h, acc[0][j]);
                wmma::mma_sync(acc[1][j], a_l[1], b_h, acc[1][j]);
            }
        }
        if (kc + 1 < NC) CP_WAIT(0);
        __syncthreads();
    }
}

// ---------------------------------------------------------------------------
// Z-gemm: Z = x @ W1_top   (M=8192, N=256, K=256), fp32 output
// ---------------------------------------------------------------------------
__global__ __launch_bounds__(256, 2)
void zgemm_kernel(const float* __restrict__ x,
                  const __nv_bfloat16* __restrict__ Bh,
                  const __nv_bfloat16* __restrict__ Bl) {
    extern __shared__ char smem[];
    const uint32_t sbase = (uint32_t)__cvta_generic_to_shared(smem);
    const int tid  = threadIdx.x;
    const int w    = tid >> 5;
    const int lane = tid & 31;
    const int bm   = blockIdx.y * 128;
    const int bn   = blockIdx.x * 128;
    const int wm   = (w & 3) * 32;
    const int wn   = (w >> 2) * 64;

    wmma::fragment<wmma::accumulator, 16, 16, 16, float> acc[2][4];
#pragma unroll
    for (int i = 0; i < 2; ++i)
#pragma unroll
        for (int j = 0; j < 4; ++j)
            wmma::fill_fragment(acc[i][j], 0.0f);

    mma_mainloop_f32A<CIN / BK_G, CIN, CCAT, 0>(
        x, bm, Bh, Bl, bn, smem, sbase, tid, wm, wn, acc);

    float* cw = (float*)smem + w * (32 * CSTR);
#pragma unroll
    for (int i = 0; i < 2; ++i)
#pragma unroll
        for (int j = 0; j < 4; ++j)
            wmma::store_matrix_sync(cw + i * 16 * CSTR + j * 16, acc[i][j],
                                    CSTR, wmma::mem_row_major);
    __syncwarp();

    const int m = bm + wm + lane;
    float4* dst = (float4*)(g_Z + (size_t)m * HDIM + bn + wn);
#pragma unroll
    for (int c = 0; c < 64; c += 4) {
        float4 o;
        o.x = cw[lane * CSTR + c];
        o.y = cw[lane * CSTR + c + 1];
        o.z = cw[lane * CSTR + c + 2];
        o.w = cw[lane * CSTR + c + 3];
        dst[c >> 2] = o;
    }
}

// ---------------------------------------------------------------------------
// S-gemm: S = x_skip @ W1_bot  (M=32768, N=256, K=128), epilogue:
//   h1 = relu( interp(Z) + S + b1 )  -> split bf16 planes
// ---------------------------------------------------------------------------
__global__ __launch_bounds__(256, 2)
void sgemm1_kernel(const float* __restrict__ x_skip,
                   const __nv_bfloat16* __restrict__ Bh,
                   const __nv_bfloat16* __restrict__ Bl,
                   const float* __restrict__ bias) {
    extern __shared__ char smem[];
    __shared__ int4   ssel[128];
    __shared__ float4 swgt[128];
    const uint32_t sbase = (uint32_t)__cvta_generic_to_shared(smem);
    const int tid  = threadIdx.x;
    const int w    = tid >> 5;
    const int lane = tid & 31;
    const int bm   = blockIdx.y * 128;
    const int bn   = blockIdx.x * 128;
    const int wm   = (w & 3) * 32;
    const int wn   = (w >> 2) * 64;
    const int batch = bm >> 13;
    const size_t zbase = (size_t)batch * NSRC;

    if (tid < 128) {
        ssel[tid] = g_selI[bm + tid];
        swgt[tid] = g_selW[bm + tid];
    }

    wmma::fragment<wmma::accumulator, 16, 16, 16, float> acc[2][4];
#pragma unroll
    for (int i = 0; i < 2; ++i)
#pragma unroll
        for (int j = 0; j < 4; ++j)
            wmma::fill_fragment(acc[i][j], 0.0f);

    mma_mainloop_f32A<CSKIP / BK_G, CSKIP, CCAT, CIN>(
        x_skip, bm, Bh, Bl, bn, smem, sbase, tid, wm, wn, acc);

    float* cw = (float*)smem + w * (32 * CSTR);
#pragma unroll
    for (int i = 0; i < 2; ++i)
#pragma unroll
        for (int j = 0; j < 4; ++j)
            wmma::store_matrix_sync(cw + i * 16 * CSTR + j * 16, acc[i][j],
                                    CSTR, wmma::mem_row_major);
    __syncwarp();

    // epilogue: per row gather 3 Z rows (coalesced across lanes), interp,
    // add S + bias, relu, split, store h1 planes.
    const int ncol0 = bn + wn;
    const float2 bias2 = *(const float2*)(bias + ncol0 + 2 * lane);
#pragma unroll 4
    for (int r = 0; r < 32; ++r) {
        const int row = wm + r;
        const int m   = bm + row;
        const int4   si = ssel[row];
        const float4 sw = swgt[row];
        const float2 z0 = *(const float2*)(g_Z + (zbase + si.x) * HDIM + ncol0 + 2 * lane);
        const float2 z1 = *(const float2*)(g_Z + (zbase + si.y) * HDIM + ncol0 + 2 * lane);
        const float2 z2 = *(const float2*)(g_Z + (zbase + si.z) * HDIM + ncol0 + 2 * lane);
        const float2 s  = *(const float2*)(cw + r * CSTR + 2 * lane);
        float vx = fmaf(sw.x, z0.x, fmaf(sw.y, z1.x, sw.z * z2.x)) * sw.w + s.x + bias2.x;
        float vy = fmaf(sw.x, z0.y, fmaf(sw.y, z1.y, sw.z * z2.y)) * sw.w + s.y + bias2.y;
        vx = fmaxf(vx, 0.0f);
        vy = fmaxf(vy, 0.0f);
        uint16_t h0, l0, h1, l1;
        split_bf16(vx, h0, l0);
        split_bf16(vy, h1, l1);
        uint32_t* dh = (uint32_t*)(g_h1_hi + (size_t)m * HDIM + ncol0);
        uint32_t* dl = (uint32_t*)(g_h1_lo + (size_t)m * HDIM + ncol0);
        dh[lane] = (uint32_t)h0 | ((uint32_t)h1 << 16);
        dl[lane] = (uint32_t)l0 | ((uint32_t)l1 << 16);
    }
}

// ---------------------------------------------------------------------------
// GEMM2 (unchanged): out = (h1 @ W2 + b2) * gate[batch]
// ---------------------------------------------------------------------------
__global__ __launch_bounds__(256, 2)
void gemm2_kernel(const __nv_bfloat16* __restrict__ Ah,
                  const __nv_bfloat16* __restrict__ Al,
                  const __nv_bfloat16* __restrict__ Bh,
                  const __nv_bfloat16* __restrict__ Bl,
                  const float* __restrict__ bias,
                  float* __restrict__ outp) {
    constexpr int KTOT = HDIM;
    constexpr int N    = COUT;
    constexpr int NC   = KTOT / BK_G;      // 8
    extern __shared__ char smem[];
    const uint32_t sbase = (uint32_t)__cvta_generic_to_shared(smem);

    const int tid  = threadIdx.x;
    const int w    = tid >> 5;
    const int lane = tid & 31;
    const int bm   = blockIdx.y * 128;
    const int bn   = blockIdx.x * 128;
    const int wm   = (w & 3) * 32;
    const int wn   = (w >> 2) * 64;

    auto stage = [&](int kc, int buf) {
#pragma unroll
        for (int u = tid; u < 2048; u += 256) {
            const int plane = u >> 9;
            const int idx   = u & 511;
            const int row   = idx >> 2;
            const int c     = idx & 3;
            const __nv_bfloat16* P =
                (plane == 0) ? Ah : (plane == 1) ? Al : (plane == 2) ? Bh : Bl;
            const int grow = (plane < 2) ? (bm + row) : (bn + row);
            const __nv_bfloat16* gsrc =
                P + (size_t)grow * KTOT + kc * BK_G + c * 8;
            uint32_t sdst = sbase + buf * BUF_B + plane * PL_B +
                            row * (STRD * 2) + c * 16;
            cp_async16(sdst, gsrc);
        }
    };

    wmma::fragment<wmma::accumulator, 16, 16, 16, float> acc[2][4];
#pragma unroll
    for (int i = 0; i < 2; ++i)
#pragma unroll
        for (int j = 0; j < 4; ++j)
            wmma::fill_fragment(acc[i][j], 0.0f);

    stage(0, 0);
    CP_COMMIT();

    for (int kc = 0; kc < NC; ++kc) {
        if (kc + 1 < NC) {
            stage(kc + 1, (kc + 1) & 1);
            CP_COMMIT();
            CP_WAIT(1);
        } else {
            CP_WAIT(0);
        }
        __syncthreads();

        const __nv_bfloat16* sb =
            (const __nv_bfloat16*)(smem + (kc & 1) * BUF_B);
        const __nv_bfloat16* sAh = sb;
        const __nv_bfloat16* sAl = sb + 128 * STRD;
        const __nv_bfloat16* sBh = sb + 2 * 128 * STRD;
        const __nv_bfloat16* sBl = sb + 3 * 128 * STRD;

#pragma unroll
        for (int kk = 0; kk < BK_G; kk += 16) {
            wmma::fragment<wmma::matrix_a, 16, 16, 16, __nv_bfloat16,
                           wmma::row_major> a_h[2], a_l[2];
#pragma unroll
            for (int i = 0; i < 2; ++i) {
                wmma::load_matrix_sync(a_h[i], sAh + (wm + i * 16) * STRD + kk, STRD);
                wmma::load_matrix_sync(a_l[i], sAl + (wm + i * 16) * STRD + kk, STRD);
            }
#pragma unroll
            for (int j = 0; j < 4; ++j) {
                wmma::fragment<wmma::matrix_b, 16, 16, 16, __nv_bfloat16,
                               wmma::col_major> b_h, b_l;
                wmma::load_matrix_sync(b_h, sBh + (wn + j * 16) * STRD + kk, STRD);
                wmma::load_matrix_sync(b_l, sBl + (wn + j * 16) * STRD + kk, STRD);
                wmma::mma_sync(acc[0][j], a_h[0], b_h, acc[0][j]);
                wmma::mma_sync(acc[1][j], a_h[1], b_h, acc[1][j]);
                wmma::mma_sync(acc[0][j], a_h[0], b_l, acc[0][j]);
                wmma::mma_sync(acc[1][j], a_h[1], b_l, acc[1][j]);
                wmma::mma_sync(acc[0][j], a_l[0], b_h, acc[0][j]);
                wmma::mma_sync(acc[1][j], a_l[1], b_h, acc[1][j]);
            }
        }
        __syncthreads();
    }

    float* cw = (float*)smem + w * (32 * CSTR);
#pragma unroll
    for (int i = 0; i < 2; ++i)
#pragma unroll
        for (int j = 0; j < 4; ++j)
            wmma::store_matrix_sync(cw + i * 16 * CSTR + j * 16, acc[i][j],
                                    CSTR, wmma::mem_row_major);
    __syncwarp();

    const int m = bm + wm + lane;
    const int ncol0 = bn + wn;
    const int batch = m >> 13;
    const float* gt = g_gate + batch * COUT;
    float4* dst = (float4*)(outp + (size_t)m * N + ncol0);
#pragma unroll
    for (int c = 0; c < 64; c += 4) {
        float4 o;
        o.x = (cw[lane * CSTR + c]     + bias[ncol0 + c])     * gt[ncol0 + c];
        o.y = (cw[lane * CSTR + c + 1] + bias[ncol0 + c + 1]) * gt[ncol0 + c + 1];
        o.z = (cw[lane * CSTR + c + 2] + bias[ncol0 + c + 2]) * gt[ncol0 + c + 2];
        o.w = (cw[lane * CSTR + c + 3] + bias[ncol0 + c + 3]) * gt[ncol0 + c + 3];
        dst[c >> 2] = o;
    }
}

// ---------------------------------------------------------------------------
extern "C" void kernel_launch(void* const* d_in, const int* in_sizes, int n_in,
                              void* d_out, int out_size) {
    const float* par      = (const float*)d_in[0];
    const float* x        = (const float*)d_in[1];
    const float* pos      = (const float*)d_in[2];
    const float* x_skip   = (const float*)d_in[3];
    const float* pos_skip = (const float*)d_in[4];
    const float* W1       = (const float*)d_in[5];
    const float* b1       = (const float*)d_in[6];
    const float* W2       = (const float*)d_in[7];
    const float* b2       = (const float*)d_in[8];
    const float* Wp       = (const float*)d_in[9];
    const float* bp       = (const float*)d_in[10];
    float* out = (float*)d_out;

    __nv_bfloat16 *p_hh, *p_hl, *p_w1h, *p_w1l, *p_w2h, *p_w2l;
    cudaGetSymbolAddress((void**)&p_hh,  g_h1_hi);
    cudaGetSymbolAddress((void**)&p_hl,  g_h1_lo);
    cudaGetSymbolAddress((void**)&p_w1h, g_w1t_hi);
    cudaGetSymbolAddress((void**)&p_w1l, g_w1t_lo);
    cudaGetSymbolAddress((void**)&p_w2h, g_w2t_hi);
    cudaGetSymbolAddress((void**)&p_w2l, g_w2t_lo);

    constexpr int SMEM_G = 2 * BUF_B;   // 81920
    cudaFuncSetAttribute(zgemm_kernel,
                         cudaFuncAttributeMaxDynamicSharedMemorySize, SMEM_G);
    cudaFuncSetAttribute(sgemm1_kernel,
                         cudaFuncAttributeMaxDynamicSharedMemorySize, SMEM_G);
    cudaFuncSetAttribute(gemm2_kernel,
                         cudaFuncAttributeMaxDynamicSharedMemorySize, SMEM_G);

    const int tail = out_size - OUT_ELEMS;
    int mode = 0;
    if (tail >= POS_ELEMS + 2 * MTOT)      mode = 2;
    else if (tail >= POS_ELEMS + MTOT)     mode = 1;

    prep_kernel<<<(POS_ELEMS + 255) / 256, 256>>>(par, Wp, bp, W1, W2,
                                                  pos_skip, out, mode, out_size);

    dim3 kg(NDST / PTS_PER_BLK, NB);       // (64, 4)
    knn_select_kernel<<<kg, 256>>>(pos, pos_skip);

    dim3 gz(HDIM / 128, MSRC / 128);       // (2, 64)
    zgemm_kernel<<<gz, 256, SMEM_G>>>(x, p_w1h, p_w1l);

    dim3 gs(HDIM / 128, MTOT / 128);       // (2, 256)
    sgemm1_kernel<<<gs, 256, SMEM_G>>>(x_skip, p_w1h, p_w1l, b1);

    dim3 g2(COUT / 128, MTOT / 128);       // (1, 256)
    gemm2_kernel<<<g2, 256, SMEM_G>>>(p_hh, p_hl, p_w2h, p_w2l, b2, out);
}

// round 15
// speedup vs baseline: 1.4421x; 1.0481x over previous
#include <cuda_runtime.h>
#include <cuda_bf16.h>
#include <math_constants.h>
#include <cstdint>
#include <mma.h>

using namespace nvcuda;

#define NB     4
#define NSRC   2048
#define NDST   8192
#define CIN    256
#define CSKIP  128
#define CCAT   384
#define HDIM   256
#define COUT   128
#define PDIM   64
#define MTOT   (NB * NDST)          // 32768
#define MSRC   (NB * NSRC)          // 8192

#define OUT_ELEMS   (MTOT * COUT)   // 4194304
#define POS_ELEMS   (MTOT * 3)      // 98304

// ---------------------------------------------------------------------------
// Scratch (__device__ globals; no allocations allowed)
// ---------------------------------------------------------------------------
__device__ float         g_Z[MSRC * HDIM];        // x @ W1_top, fp32 (8 MB)
__device__ __nv_bfloat16 g_h1_hi[MTOT * HDIM];    // GEMM2 A hi plane
__device__ __nv_bfloat16 g_h1_lo[MTOT * HDIM];
__device__ __nv_bfloat16 g_w1t_hi[HDIM * CCAT];   // W1^T planes [N=256, K=384]
__device__ __nv_bfloat16 g_w1t_lo[HDIM * CCAT];
__device__ __nv_bfloat16 g_w2t_hi[COUT * HDIM];   // W2^T planes [N=128, K=256]
__device__ __nv_bfloat16 g_w2t_lo[COUT * HDIM];
__device__ float g_gate[NB * COUT];
__device__ int4   g_selI[MTOT];                   // j0, j1, j2, pad
__device__ float4 g_selW[MTOT];                   // w0, w1, w2, inv_den

// fp32 -> bf16 hi/lo split
__device__ __forceinline__ void split_bf16(float v, uint16_t& h, uint16_t& l) {
    __nv_bfloat16 hb = __float2bfloat16_rn(v);
    float r = v - __bfloat162float(hb);
    __nv_bfloat16 lb = __float2bfloat16_rn(r);
    h = __bfloat16_as_ushort(hb);
    l = __bfloat16_as_ushort(lb);
}

// cp.async helpers (sm_80 baseline — legal on sm_103 target)
__device__ __forceinline__ void cp_async16(uint32_t dst, const void* src) {
    asm volatile("cp.async.ca.shared.global [%0], [%1], 16;"
                 :: "r"(dst), "l"(src) : "memory");
}
#define CP_COMMIT() asm volatile("cp.async.commit_group;" ::: "memory")
#define CP_WAIT(n)  asm volatile("cp.async.wait_group %0;" :: "n"(n) : "memory")

// ---------------------------------------------------------------------------
// prep: gate + weight transpose/split + output tail (pos_skip, batch_skip)
// ---------------------------------------------------------------------------
__global__ void prep_kernel(const float* __restrict__ par,
                            const float* __restrict__ Wp,
                            const float* __restrict__ bp,
                            const float* __restrict__ W1,
                            const float* __restrict__ W2,
                            const float* __restrict__ pos_skip,
                            float* __restrict__ out, int mode, int out_size) {
    int i = blockIdx.x * 256 + threadIdx.x;
    if (i < NB * COUT) {
        int b = i >> 7, n = i & 127;
        float acc = bp[n];
        const float* pe = par + b * PDIM;
#pragma unroll
        for (int p = 0; p < PDIM; ++p)
            acc = fmaf(pe[p], Wp[p * COUT + n], acc);
        g_gate[i] = fmaxf(acc, 0.0f);
    }
    if (i < CCAT * HDIM) {
        int k = i / HDIM, n = i % HDIM;
        uint16_t h, l;
        split_bf16(W1[i], h, l);
        g_w1t_hi[n * CCAT + k] = __ushort_as_bfloat16(h);
        g_w1t_lo[n * CCAT + k] = __ushort_as_bfloat16(l);
    }
    if (i < HDIM * COUT) {
        int k = i / COUT, n = i % COUT;
        uint16_t h, l;
        split_bf16(W2[i], h, l);
        g_w2t_hi[n * HDIM + k] = __ushort_as_bfloat16(h);
        g_w2t_lo[n * HDIM + k] = __ushort_as_bfloat16(l);
    }
    // output tail
    if (i < POS_ELEMS && OUT_ELEMS + i < out_size)
        out[OUT_ELEMS + i] = pos_skip[i];
    if (i < MTOT) {
        if (mode == 1) {
            int o = OUT_ELEMS + POS_ELEMS + i;
            if (o < out_size) out[o] = (float)(i >> 13);
        } else if (mode == 2) {
            int o = OUT_ELEMS + POS_ELEMS + 2 * i;
            if (o + 1 < out_size)
                ((long long*)(out + OUT_ELEMS + POS_ELEMS))[i] = (long long)(i >> 13);
        }
    }
}

// ---------------------------------------------------------------------------
// Shared GEMM tile constants
// ---------------------------------------------------------------------------
#define BK_G   32
#define STRD   40                          // 80B row stride: conflict-free LDSM
#define PL_B   (128 * STRD * 2)            // plane bytes = 10240
#define BUF_B  (4 * PL_B)                  // 4 planes per buffer = 40960
#define CSTR   68                          // epilogue C buffer stride (floats)

// ---------------------------------------------------------------------------
// Core split-bf16 MMA mainloop (A fp32 staged+split on the fly, B planes).
// ---------------------------------------------------------------------------
template<int NC, int AK, int BSTRIDE, int BOFF>
__device__ __forceinline__ void mma_mainloop_f32A(
    const float* __restrict__ A, int bm,
    const __nv_bfloat16* __restrict__ Bh,
    const __nv_bfloat16* __restrict__ Bl, int bn,
    char* smem, uint32_t sbase, int tid, int wm, int wn,
    wmma::fragment<wmma::accumulator, 16, 16, 16, float> (&acc)[2][4]) {

    const int arow = tid >> 1;
    const int aseg = tid & 1;

    auto stageA = [&](int kc, int buf) {
        const float* src = A + (size_t)(bm + arow) * AK + kc * BK_G + aseg * 16;
        float v[16];
#pragma unroll
        for (int q = 0; q < 4; ++q) {
            float4 s = *(const float4*)(src + q * 4);
            v[q * 4 + 0] = s.x; v[q * 4 + 1] = s.y;
            v[q * 4 + 2] = s.z; v[q * 4 + 3] = s.w;
        }
        uint32_t hp[8], lp[8];
#pragma unroll
        for (int e = 0; e < 16; e += 2) {
            uint16_t h0, l0, h1, l1;
            split_bf16(v[e],     h0, l0);
            split_bf16(v[e + 1], h1, l1);
            hp[e >> 1] = (uint32_t)h0 | ((uint32_t)h1 << 16);
            lp[e >> 1] = (uint32_t)l0 | ((uint32_t)l1 << 16);
        }
        char* base = smem + buf * BUF_B;
        uint4* dh = (uint4*)(base + arow * (STRD * 2) + aseg * 32);
        uint4* dl = (uint4*)(base + PL_B + arow * (STRD * 2) + aseg * 32);
        dh[0] = make_uint4(hp[0], hp[1], hp[2], hp[3]);
        dh[1] = make_uint4(hp[4], hp[5], hp[6], hp[7]);
        dl[0] = make_uint4(lp[0], lp[1], lp[2], lp[3]);
        dl[1] = make_uint4(lp[4], lp[5], lp[6], lp[7]);
    };

    auto stageB = [&](int kc, int buf) {
#pragma unroll
        for (int u = tid; u < 1024; u += 256) {
            const int plane = u >> 9;
            const int idx   = u & 511;
            const int row   = idx >> 2;
            const int c     = idx & 3;
            const __nv_bfloat16* P = plane ? Bl : Bh;
            const __nv_bfloat16* gsrc =
                P + (size_t)(bn + row) * BSTRIDE + BOFF + kc * BK_G + c * 8;
            uint32_t sdst = sbase + buf * BUF_B + (2 + plane) * PL_B +
                            row * (STRD * 2) + c * 16;
            cp_async16(sdst, gsrc);
        }
    };

    stageB(0, 0);
    CP_COMMIT();
    stageA(0, 0);
    CP_WAIT(0);
    __syncthreads();

    for (int kc = 0; kc < NC; ++kc) {
        if (kc + 1 < NC) {
            stageB(kc + 1, (kc + 1) & 1);
            CP_COMMIT();
            stageA(kc + 1, (kc + 1) & 1);
        }

        const __nv_bfloat16* sb =
            (const __nv_bfloat16*)(smem + (kc & 1) * BUF_B);
        const __nv_bfloat16* sAh = sb;
        const __nv_bfloat16* sAl = sb + 128 * STRD;
        const __nv_bfloat16* sBh = sb + 2 * 128 * STRD;
        const __nv_bfloat16* sBl = sb + 3 * 128 * STRD;

#pragma unroll
        for (int kk = 0; kk < BK_G; kk += 16) {
            wmma::fragment<wmma::matrix_a, 16, 16, 16, __nv_bfloat16,
                           wmma::row_major> a_h[2], a_l[2];
#pragma unroll
            for (int i = 0; i < 2; ++i) {
                wmma::load_matrix_sync(a_h[i], sAh + (wm + i * 16) * STRD + kk, STRD);
                wmma::load_matrix_sync(a_l[i], sAl + (wm + i * 16) * STRD + kk, STRD);
            }
#pragma unroll
            for (int j = 0; j < 4; ++j) {
                wmma::fragment<wmma::matrix_b, 16, 16, 16, __nv_bfloat16,
                               wmma::col_major> b_h, b_l;
                wmma::load_matrix_sync(b_h, sBh + (wn + j * 16) * STRD + kk, STRD);
                wmma::load_matrix_sync(b_l, sBl + (wn + j * 16) * STRD + kk, STRD);
                wmma::mma_sync(acc[0][j], a_h[0], b_h, acc[0][j]);
                wmma::mma_sync(acc[1][j], a_h[1], b_h, acc[1][j]);
                wmma::mma_sync(acc[0][j], a_h[0], b_l, acc[0][j]);
                wmma::mma_sync(acc[1][j], a_h[1], b_l, acc[1][j]);
                wmma::mma_sync(acc[0][j], a_l[0], b_h, acc[0][j]);
                wmma::mma_sync(acc[1][j], a_l[1], b_h, acc[1][j]);
            }
        }
        if (kc + 1 < NC) CP_WAIT(0);
        __syncthreads();
    }
}

// ---------------------------------------------------------------------------
// Merged KNN-selection + Z-gemm kernel.
//   blockIdx.x <  KNN_CTAS : KNN selection (pair-split, stable top-3)
//   blockIdx.x >= KNN_CTAS : Z = x @ W1_top  tile (fp32 out to g_Z)
// Independent work units overlap on the chip instead of serializing.
// ---------------------------------------------------------------------------
#define PTS_PER_BLK 128
#define KNN_CTAS    (NB * NDST / PTS_PER_BLK)   // 256
#define ZG_CTAS     ((MSRC / 128) * (HDIM / 128))  // 128

__global__ __launch_bounds__(256, 2)
void knz_kernel(const float* __restrict__ pos,
                const float* __restrict__ pos_skip,
                const float* __restrict__ x,
                const __nv_bfloat16* __restrict__ Bh,
                const __nv_bfloat16* __restrict__ Bl) {
    extern __shared__ char smem[];
    const int tid = threadIdx.x;

    if (blockIdx.x < KNN_CTAS) {
        // ---------------- KNN selection path ----------------
        float4* spos = (float4*)smem;                 // 32 KB of the 80 KB
        const int bx = blockIdx.x & 63;
        const int b  = blockIdx.x >> 6;

        const float* sp = pos + (size_t)b * NSRC * 3;
        for (int i = tid; i < NSRC; i += 256) {
            float px = sp[i * 3 + 0];
            float py = sp[i * 3 + 1];
            float pz = sp[i * 3 + 2];
            float s2 = __fmaf_rn(pz, pz, __fmaf_rn(py, py, __fmul_rn(px, px)));
            spos[i] = make_float4(px, py, pz, s2);
        }
        __syncthreads();

        const int slot   = tid >> 1;
        const int parity = tid & 1;
        const int m  = b * NDST + bx * PTS_PER_BLK + slot;
        const float dx = pos_skip[m * 3 + 0];
        const float dy = pos_skip[m * 3 + 1];
        const float dz = pos_skip[m * 3 + 2];
        const float dd = __fmaf_rn(dz, dz, __fmaf_rn(dy, dy, __fmul_rn(dx, dx)));

        float a0 = CUDART_INF_F, a1 = CUDART_INF_F, a2 = CUDART_INF_F;
        int   q0 = 0, q1 = 0, q2 = 0;

#pragma unroll 4
        for (int j = parity; j < NSRC; j += 2) {
            float4 c = spos[j];
            float d2 = __fadd_rn(__fadd_rn(dd, c.w),
                       -__fmul_rn(2.0f,
                        __fmaf_rn(dz, c.z, __fmaf_rn(dy, c.y, __fmul_rn(dx, c.x)))));
            bool p0 = d2 < a0, p1 = d2 < a1, p2 = d2 < a2;
            q2 = p1 ? q1 : (p2 ? j  : q2);
            a2 = p1 ? a1 : (p2 ? d2 : a2);
            q1 = p0 ? q0 : (p1 ? j  : q1);
            a1 = p0 ? a0 : (p1 ? d2 : a1);
            q0 = p0 ? j  : q0;
            a0 = p0 ? d2 : a0;
        }

        const unsigned FULL = 0xffffffffu;
        float oa0 = __shfl_down_sync(FULL, a0, 1);
        float oa1 = __shfl_down_sync(FULL, a1, 1);
        float oa2 = __shfl_down_sync(FULL, a2, 1);
        int   oq0 = __shfl_down_sync(FULL, q0, 1);
        int   oq1 = __shfl_down_sync(FULL, q1, 1);
        int   oq2 = __shfl_down_sync(FULL, q2, 1);

        if (parity == 0) {
#pragma unroll
            for (int t = 0; t < 3; ++t) {
                float d  = (t == 0) ? oa0 : (t == 1) ? oa1 : oa2;
                int   jj = (t == 0) ? oq0 : (t == 1) ? oq1 : oq2;
                bool lt0 = (d < a0) || (d == a0 && jj < q0);
                bool lt1 = (d < a1) || (d == a1 && jj < q1);
                bool lt2 = (d < a2) || (d == a2 && jj < q2);
                q2 = lt1 ? q1 : (lt2 ? jj : q2);
                a2 = lt1 ? a1 : (lt2 ? d  : a2);
                q1 = lt0 ? q0 : (lt1 ? jj : q1);
                a1 = lt0 ? a0 : (lt1 ? d  : a1);
                q0 = lt0 ? jj : q0;
                a0 = lt0 ? d  : a0;
            }
            float w0 = __fdiv_rn(1.0f, fmaxf(a0, 1e-16f));
            float w1 = __fdiv_rn(1.0f, fmaxf(a1, 1e-16f));
            float w2 = __fdiv_rn(1.0f, fmaxf(a2, 1e-16f));
            float den = __fadd_rn(__fadd_rn(w0, w1), w2);
            g_selI[m] = make_int4(q0, q1, q2, 0);
            g_selW[m] = make_float4(w0, w1, w2, __fdiv_rn(1.0f, den));
        }
    } else {
        // ---------------- Z-gemm path ----------------
        const int zb = blockIdx.x - KNN_CTAS;
        const uint32_t sbase = (uint32_t)__cvta_generic_to_shared(smem);
        const int w    = tid >> 5;
        const int lane = tid & 31;
        const int bm   = (zb >> 1) * 128;
        const int bn   = (zb & 1) * 128;
        const int wm   = (w & 3) * 32;
        const int wn   = (w >> 2) * 64;

        wmma::fragment<wmma::accumulator, 16, 16, 16, float> acc[2][4];
#pragma unroll
        for (int i = 0; i < 2; ++i)
#pragma unroll
            for (int j = 0; j < 4; ++j)
                wmma::fill_fragment(acc[i][j], 0.0f);

        mma_mainloop_f32A<CIN / BK_G, CIN, CCAT, 0>(
            x, bm, Bh, Bl, bn, smem, sbase, tid, wm, wn, acc);

        float* cw = (float*)smem + w * (32 * CSTR);
#pragma unroll
        for (int i = 0; i < 2; ++i)
#pragma unroll
            for (int j = 0; j < 4; ++j)
                wmma::store_matrix_sync(cw + i * 16 * CSTR + j * 16, acc[i][j],
                                        CSTR, wmma::mem_row_major);
        __syncwarp();

        const int m = bm + wm + lane;
        float4* dst = (float4*)(g_Z + (size_t)m * HDIM + bn + wn);
#pragma unroll
        for (int c = 0; c < 64; c += 4) {
            float4 o;
            o.x = cw[lane * CSTR + c];
            o.y = cw[lane * CSTR + c + 1];
            o.z = cw[lane * CSTR + c + 2];
            o.w = cw[lane * CSTR + c + 3];
            dst[c >> 2] = o;
        }
    }
}

// ---------------------------------------------------------------------------
// S-gemm: S = x_skip @ W1_bot  (M=32768, N=256, K=128), epilogue:
//   h1 = relu( interp(Z) + S + b1 )  -> split bf16 planes
// ---------------------------------------------------------------------------
__global__ __launch_bounds__(256, 2)
void sgemm1_kernel(const float* __restrict__ x_skip,
                   const __nv_bfloat16* __restrict__ Bh,
                   const __nv_bfloat16* __restrict__ Bl,
                   const float* __restrict__ bias) {
    extern __shared__ char smem[];
    __shared__ int4   ssel[128];
    __shared__ float4 swgt[128];
    const uint32_t sbase = (uint32_t)__cvta_generic_to_shared(smem);
    const int tid  = threadIdx.x;
    const int w    = tid >> 5;
    const int lane = tid & 31;
    const int bm   = blockIdx.y * 128;
    const int bn   = blockIdx.x * 128;
    const int wm   = (w & 3) * 32;
    const int wn   = (w >> 2) * 64;
    const int batch = bm >> 13;
    const size_t zbase = (size_t)batch * NSRC;

    if (tid < 128) {
        ssel[tid] = g_selI[bm + tid];
        swgt[tid] = g_selW[bm + tid];
    }

    wmma::fragment<wmma::accumulator, 16, 16, 16, float> acc[2][4];
#pragma unroll
    for (int i = 0; i < 2; ++i)
#pragma unroll
        for (int j = 0; j < 4; ++j)
            wmma::fill_fragment(acc[i][j], 0.0f);

    mma_mainloop_f32A<CSKIP / BK_G, CSKIP, CCAT, CIN>(
        x_skip, bm, Bh, Bl, bn, smem, sbase, tid, wm, wn, acc);

    float* cw = (float*)smem + w * (32 * CSTR);
#pragma unroll
    for (int i = 0; i < 2; ++i)
#pragma unroll
        for (int j = 0; j < 4; ++j)
            wmma::store_matrix_sync(cw + i * 16 * CSTR + j * 16, acc[i][j],
                                    CSTR, wmma::mem_row_major);
    __syncwarp();

    const int ncol0 = bn + wn;
    const float2 bias2 = *(const float2*)(bias + ncol0 + 2 * lane);
#pragma unroll 4
    for (int r = 0; r < 32; ++r) {
        const int row = wm + r;
        const int m   = bm + row;
        const int4   si = ssel[row];
        const float4 sw = swgt[row];
        const float2 z0 = *(const float2*)(g_Z + (zbase + si.x) * HDIM + ncol0 + 2 * lane);
        const float2 z1 = *(const float2*)(g_Z + (zbase + si.y) * HDIM + ncol0 + 2 * lane);
        const float2 z2 = *(const float2*)(g_Z + (zbase + si.z) * HDIM + ncol0 + 2 * lane);
        const float2 s  = *(const float2*)(cw + r * CSTR + 2 * lane);
        float vx = fmaf(sw.x, z0.x, fmaf(sw.y, z1.x, sw.z * z2.x)) * sw.w + s.x + bias2.x;
        float vy = fmaf(sw.x, z0.y, fmaf(sw.y, z1.y, sw.z * z2.y)) * sw.w + s.y + bias2.y;
        vx = fmaxf(vx, 0.0f);
        vy = fmaxf(vy, 0.0f);
        uint16_t h0, l0, h1, l1;
        split_bf16(vx, h0, l0);
        split_bf16(vy, h1, l1);
        uint32_t* dh = (uint32_t*)(g_h1_hi + (size_t)m * HDIM + ncol0);
        uint32_t* dl = (uint32_t*)(g_h1_lo + (size_t)m * HDIM + ncol0);
        dh[lane] = (uint32_t)h0 | ((uint32_t)h1 << 16);
        dl[lane] = (uint32_t)l0 | ((uint32_t)l1 << 16);
    }
}

// ---------------------------------------------------------------------------
// GEMM2 (unchanged): out = (h1 @ W2 + b2) * gate[batch]
// ---------------------------------------------------------------------------
__global__ __launch_bounds__(256, 2)
void gemm2_kernel(const __nv_bfloat16* __restrict__ Ah,
                  const __nv_bfloat16* __restrict__ Al,
                  const __nv_bfloat16* __restrict__ Bh,
                  const __nv_bfloat16* __restrict__ Bl,
                  const float* __restrict__ bias,
                  float* __restrict__ outp) {
    constexpr int KTOT = HDIM;
    constexpr int N    = COUT;
    constexpr int NC   = KTOT / BK_G;      // 8
    extern __shared__ char smem[];
    const uint32_t sbase = (uint32_t)__cvta_generic_to_shared(smem);

    const int tid  = threadIdx.x;
    const int w    = tid >> 5;
    const int lane = tid & 31;
    const int bm   = blockIdx.y * 128;
    const int bn   = blockIdx.x * 128;
    const int wm   = (w & 3) * 32;
    const int wn   = (w >> 2) * 64;

    auto stage = [&](int kc, int buf) {
#pragma unroll
        for (int u = tid; u < 2048; u += 256) {
            const int plane = u >> 9;
            const int idx   = u & 511;
            const int row   = idx >> 2;
            const int c     = idx & 3;
            const __nv_bfloat16* P =
                (plane == 0) ? Ah : (plane == 1) ? Al : (plane == 2) ? Bh : Bl;
            const int grow = (plane < 2) ? (bm + row) : (bn + row);
            const __nv_bfloat16* gsrc =
                P + (size_t)grow * KTOT + kc * BK_G + c * 8;
            uint32_t sdst = sbase + buf * BUF_B + plane * PL_B +
                            row * (STRD * 2) + c * 16;
            cp_async16(sdst, gsrc);
        }
    };

    wmma::fragment<wmma::accumulator, 16, 16, 16, float> acc[2][4];
#pragma unroll
    for (int i = 0; i < 2; ++i)
#pragma unroll
        for (int j = 0; j < 4; ++j)
            wmma::fill_fragment(acc[i][j], 0.0f);

    stage(0, 0);
    CP_COMMIT();

    for (int kc = 0; kc < NC; ++kc) {
        if (kc + 1 < NC) {
            stage(kc + 1, (kc + 1) & 1);
            CP_COMMIT();
            CP_WAIT(1);
        } else {
            CP_WAIT(0);
        }
        __syncthreads();

        const __nv_bfloat16* sb =
            (const __nv_bfloat16*)(smem + (kc & 1) * BUF_B);
        const __nv_bfloat16* sAh = sb;
        const __nv_bfloat16* sAl = sb + 128 * STRD;
        const __nv_bfloat16* sBh = sb + 2 * 128 * STRD;
        const __nv_bfloat16* sBl = sb + 3 * 128 * STRD;

#pragma unroll
        for (int kk = 0; kk < BK_G; kk += 16) {
            wmma::fragment<wmma::matrix_a, 16, 16, 16, __nv_bfloat16,
                           wmma::row_major> a_h[2], a_l[2];
#pragma unroll
            for (int i = 0; i < 2; ++i) {
                wmma::load_matrix_sync(a_h[i], sAh + (wm + i * 16) * STRD + kk, STRD);
                wmma::load_matrix_sync(a_l[i], sAl + (wm + i * 16) * STRD + kk, STRD);
            }
#pragma unroll
            for (int j = 0; j < 4; ++j) {
                wmma::fragment<wmma::matrix_b, 16, 16, 16, __nv_bfloat16,
                               wmma::col_major> b_h, b_l;
                wmma::load_matrix_sync(b_h, sBh + (wn + j * 16) * STRD + kk, STRD);
                wmma::load_matrix_sync(b_l, sBl + (wn + j * 16) * STRD + kk, STRD);
                wmma::mma_sync(acc[0][j], a_h[0], b_h, acc[0][j]);
                wmma::mma_sync(acc[1][j], a_h[1], b_h, acc[1][j]);
                wmma::mma_sync(acc[0][j], a_h[0], b_l, acc[0][j]);
                wmma::mma_sync(acc[1][j], a_h[1], b_l, acc[1][j]);
                wmma::mma_sync(acc[0][j], a_l[0], b_h, acc[0][j]);
                wmma::mma_sync(acc[1][j], a_l[1], b_h, acc[1][j]);
            }
        }
        __syncthreads();
    }

    float* cw = (float*)smem + w * (32 * CSTR);
#pragma unroll
    for (int i = 0; i < 2; ++i)
#pragma unroll
        for (int j = 0; j < 4; ++j)
            wmma::store_matrix_sync(cw + i * 16 * CSTR + j * 16, acc[i][j],
                                    CSTR, wmma::mem_row_major);
    __syncwarp();

    const int m = bm + wm + lane;
    const int ncol0 = bn + wn;
    const int batch = m >> 13;
    const float* gt = g_gate + batch * COUT;
    float4* dst = (float4*)(outp + (size_t)m * N + ncol0);
#pragma unroll
    for (int c = 0; c < 64; c += 4) {
        float4 o;
        o.x = (cw[lane * CSTR + c]     + bias[ncol0 + c])     * gt[ncol0 + c];
        o.y = (cw[lane * CSTR + c + 1] + bias[ncol0 + c + 1]) * gt[ncol0 + c + 1];
        o.z = (cw[lane * CSTR + c + 2] + bias[ncol0 + c + 2]) * gt[ncol0 + c + 2];
        o.w = (cw[lane * CSTR + c + 3] + bias[ncol0 + c + 3]) * gt[ncol0 + c + 3];
        dst[c >> 2] = o;
    }
}

// ---------------------------------------------------------------------------
extern "C" void kernel_launch(void* const* d_in, const int* in_sizes, int n_in,
                              void* d_out, int out_size) {
    const float* par      = (const float*)d_in[0];
    const float* x        = (const float*)d_in[1];
    const float* pos      = (const float*)d_in[2];
    const float* x_skip   = (const float*)d_in[3];
    const float* pos_skip = (const float*)d_in[4];
    const float* W1       = (const float*)d_in[5];
    const float* b1       = (const float*)d_in[6];
    const float* W2       = (const float*)d_in[7];
    const float* b2       = (const float*)d_in[8];
    const float* Wp       = (const float*)d_in[9];
    const float* bp       = (const float*)d_in[10];
    float* out = (float*)d_out;

    __nv_bfloat16 *p_hh, *p_hl, *p_w1h, *p_w1l, *p_w2h, *p_w2l;
    cudaGetSymbolAddress((void**)&p_hh,  g_h1_hi);
    cudaGetSymbolAddress((void**)&p_hl,  g_h1_lo);
    cudaGetSymbolAddress((void**)&p_w1h, g_w1t_hi);
    cudaGetSymbolAddress((void**)&p_w1l, g_w1t_lo);
    cudaGetSymbolAddress((void**)&p_w2h, g_w2t_hi);
    cudaGetSymbolAddress((void**)&p_w2l, g_w2t_lo);

    constexpr int SMEM_G = 2 * BUF_B;   // 81920
    cudaFuncSetAttribute(knz_kernel,
                         cudaFuncAttributeMaxDynamicSharedMemorySize, SMEM_G);
    cudaFuncSetAttribute(sgemm1_kernel,
                         cudaFuncAttributeMaxDynamicSharedMemorySize, SMEM_G);
    cudaFuncSetAttribute(gemm2_kernel,
                         cudaFuncAttributeMaxDynamicSharedMemorySize, SMEM_G);

    const int tail = out_size - OUT_ELEMS;
    int mode = 0;
    if (tail >= POS_ELEMS + 2 * MTOT)      mode = 2;
    else if (tail >= POS_ELEMS + MTOT)     mode = 1;

    prep_kernel<<<(POS_ELEMS + 255) / 256, 256>>>(par, Wp, bp, W1, W2,
                                                  pos_skip, out, mode, out_size);

    knz_kernel<<<KNN_CTAS + ZG_CTAS, 256, SMEM_G>>>(pos, pos_skip, x,
                                                    p_w1h, p_w1l);

    dim3 gs(HDIM / 128, MTOT / 128);       // (2, 256)
    sgemm1_kernel<<<gs, 256, SMEM_G>>>(x_skip, p_w1h, p_w1l, b1);

    dim3 g2(COUT / 128, MTOT / 128);       // (1, 256)
    gemm2_kernel<<<g2, 256, SMEM_G>>>(p_hh, p_hl, p_w2h, p_w2l, b2, out);
}

// round 16
// speedup vs baseline: 1.6207x; 1.1238x over previous
#include <cuda_runtime.h>
#include <cuda_bf16.h>
#include <math_constants.h>
#include <cstdint>
#include <mma.h>

using namespace nvcuda;

#define NB     4
#define NSRC   2048
#define NDST   8192
#define CIN    256
#define CSKIP  128
#define CCAT   384
#define HDIM   256
#define COUT   128
#define PDIM   64
#define MTOT   (NB * NDST)          // 32768
#define MSRC   (NB * NSRC)          // 8192

#define OUT_ELEMS   (MTOT * COUT)   // 4194304
#define POS_ELEMS   (MTOT * 3)      // 98304

// ---------------------------------------------------------------------------
// Scratch (__device__ globals; no allocations allowed)
// ---------------------------------------------------------------------------
__device__ float         g_Z[MSRC * HDIM];        // x @ W1_top, fp32 (8 MB)
__device__ __nv_bfloat16 g_h1_hi[MTOT * HDIM];    // GEMM2 A hi plane
__device__ __nv_bfloat16 g_h1_lo[MTOT * HDIM];
__device__ __nv_bfloat16 g_w1t_hi[HDIM * CCAT];   // W1^T planes [N=256, K=384]
__device__ __nv_bfloat16 g_w1t_lo[HDIM * CCAT];
__device__ __nv_bfloat16 g_w2t_hi[COUT * HDIM];   // W2^T planes [N=128, K=256]
__device__ __nv_bfloat16 g_w2t_lo[COUT * HDIM];
__device__ float g_gate[NB * COUT];
__device__ int4   g_selI[MTOT];                   // j0, j1, j2, pad
__device__ float4 g_selW[MTOT];                   // w0, w1, w2, inv_den

// fp32 -> bf16 hi/lo split
__device__ __forceinline__ void split_bf16(float v, uint16_t& h, uint16_t& l) {
    __nv_bfloat16 hb = __float2bfloat16_rn(v);
    float r = v - __bfloat162float(hb);
    __nv_bfloat16 lb = __float2bfloat16_rn(r);
    h = __bfloat16_as_ushort(hb);
    l = __bfloat16_as_ushort(lb);
}

// cp.async helpers (sm_80 baseline — legal on sm_103 target)
__device__ __forceinline__ void cp_async16(uint32_t dst, const void* src) {
    asm volatile("cp.async.ca.shared.global [%0], [%1], 16;"
                 :: "r"(dst), "l"(src) : "memory");
}
#define CP_COMMIT() asm volatile("cp.async.commit_group;" ::: "memory")
#define CP_WAIT(n)  asm volatile("cp.async.wait_group %0;" :: "n"(n) : "memory")

// ---------------------------------------------------------------------------
// prep: gate + weight transpose/split + output tail (pos_skip, batch_skip)
// ---------------------------------------------------------------------------
__global__ void prep_kernel(const float* __restrict__ par,
                            const float* __restrict__ Wp,
                            const float* __restrict__ bp,
                            const float* __restrict__ W1,
                            const float* __restrict__ W2,
                            const float* __restrict__ pos_skip,
                            float* __restrict__ out, int mode, int out_size) {
    int i = blockIdx.x * 256 + threadIdx.x;
    if (i < NB * COUT) {
        int b = i >> 7, n = i & 127;
        float acc = bp[n];
        const float* pe = par + b * PDIM;
#pragma unroll
        for (int p = 0; p < PDIM; ++p)
            acc = fmaf(pe[p], Wp[p * COUT + n], acc);
        g_gate[i] = fmaxf(acc, 0.0f);
    }
    if (i < CCAT * HDIM) {
        int k = i / HDIM, n = i % HDIM;
        uint16_t h, l;
        split_bf16(W1[i], h, l);
        g_w1t_hi[n * CCAT + k] = __ushort_as_bfloat16(h);
        g_w1t_lo[n * CCAT + k] = __ushort_as_bfloat16(l);
    }
    if (i < HDIM * COUT) {
        int k = i / COUT, n = i % COUT;
        uint16_t h, l;
        split_bf16(W2[i], h, l);
        g_w2t_hi[n * HDIM + k] = __ushort_as_bfloat16(h);
        g_w2t_lo[n * HDIM + k] = __ushort_as_bfloat16(l);
    }
    // output tail
    if (i < POS_ELEMS && OUT_ELEMS + i < out_size)
        out[OUT_ELEMS + i] = pos_skip[i];
    if (i < MTOT) {
        if (mode == 1) {
            int o = OUT_ELEMS + POS_ELEMS + i;
            if (o < out_size) out[o] = (float)(i >> 13);
        } else if (mode == 2) {
            int o = OUT_ELEMS + POS_ELEMS + 2 * i;
            if (o + 1 < out_size)
                ((long long*)(out + OUT_ELEMS + POS_ELEMS))[i] = (long long)(i >> 13);
        }
    }
}

// ---------------------------------------------------------------------------
// Shared GEMM tile constants
// ---------------------------------------------------------------------------
#define BK_G   32
#define STRD   40                          // 80B row stride: conflict-free LDSM
#define PL_B   (128 * STRD * 2)            // plane bytes = 10240
#define BUF_B  (4 * PL_B)                  // 4 planes per buffer = 40960
#define CSTR   68                          // epilogue C buffer stride (floats)

// ---------------------------------------------------------------------------
// Core split-bf16 MMA mainloop (A fp32 staged+split on the fly, B planes).
// ---------------------------------------------------------------------------
template<int NC, int AK, int BSTRIDE, int BOFF>
__device__ __forceinline__ void mma_mainloop_f32A(
    const float* __restrict__ A, int bm,
    const __nv_bfloat16* __restrict__ Bh,
    const __nv_bfloat16* __restrict__ Bl, int bn,
    char* smem, uint32_t sbase, int tid, int wm, int wn,
    wmma::fragment<wmma::accumulator, 16, 16, 16, float> (&acc)[2][4]) {

    const int arow = tid >> 1;
    const int aseg = tid & 1;

    auto stageA = [&](int kc, int buf) {
        const float* src = A + (size_t)(bm + arow) * AK + kc * BK_G + aseg * 16;
        float v[16];
#pragma unroll
        for (int q = 0; q < 4; ++q) {
            float4 s = *(const float4*)(src + q * 4);
            v[q * 4 + 0] = s.x; v[q * 4 + 1] = s.y;
            v[q * 4 + 2] = s.z; v[q * 4 + 3] = s.w;
        }
        uint32_t hp[8], lp[8];
#pragma unroll
        for (int e = 0; e < 16; e += 2) {
            uint16_t h0, l0, h1, l1;
            split_bf16(v[e],     h0, l0);
            split_bf16(v[e + 1], h1, l1);
            hp[e >> 1] = (uint32_t)h0 | ((uint32_t)h1 << 16);
            lp[e >> 1] = (uint32_t)l0 | ((uint32_t)l1 << 16);
        }
        char* base = smem + buf * BUF_B;
        uint4* dh = (uint4*)(base + arow * (STRD * 2) + aseg * 32);
        uint4* dl = (uint4*)(base + PL_B + arow * (STRD * 2) + aseg * 32);
        dh[0] = make_uint4(hp[0], hp[1], hp[2], hp[3]);
        dh[1] = make_uint4(hp[4], hp[5], hp[6], hp[7]);
        dl[0] = make_uint4(lp[0], lp[1], lp[2], lp[3]);
        dl[1] = make_uint4(lp[4], lp[5], lp[6], lp[7]);
    };

    auto stageB = [&](int kc, int buf) {
#pragma unroll
        for (int u = tid; u < 1024; u += 256) {
            const int plane = u >> 9;
            const int idx   = u & 511;
            const int row   = idx >> 2;
            const int c     = idx & 3;
            const __nv_bfloat16* P = plane ? Bl : Bh;
            const __nv_bfloat16* gsrc =
                P + (size_t)(bn + row) * BSTRIDE + BOFF + kc * BK_G + c * 8;
            uint32_t sdst = sbase + buf * BUF_B + (2 + plane) * PL_B +
                            row * (STRD * 2) + c * 16;
            cp_async16(sdst, gsrc);
        }
    };

    stageB(0, 0);
    CP_COMMIT();
    stageA(0, 0);
    CP_WAIT(0);
    __syncthreads();

    for (int kc = 0; kc < NC; ++kc) {
        if (kc + 1 < NC) {
            stageB(kc + 1, (kc + 1) & 1);
            CP_COMMIT();
            stageA(kc + 1, (kc + 1) & 1);
        }

        const __nv_bfloat16* sb =
            (const __nv_bfloat16*)(smem + (kc & 1) * BUF_B);
        const __nv_bfloat16* sAh = sb;
        const __nv_bfloat16* sAl = sb + 128 * STRD;
        const __nv_bfloat16* sBh = sb + 2 * 128 * STRD;
        const __nv_bfloat16* sBl = sb + 3 * 128 * STRD;

#pragma unroll
        for (int kk = 0; kk < BK_G; kk += 16) {
            wmma::fragment<wmma::matrix_a, 16, 16, 16, __nv_bfloat16,
                           wmma::row_major> a_h[2], a_l[2];
#pragma unroll
            for (int i = 0; i < 2; ++i) {
                wmma::load_matrix_sync(a_h[i], sAh + (wm + i * 16) * STRD + kk, STRD);
                wmma::load_matrix_sync(a_l[i], sAl + (wm + i * 16) * STRD + kk, STRD);
            }
#pragma unroll
            for (int j = 0; j < 4; ++j) {
                wmma::fragment<wmma::matrix_b, 16, 16, 16, __nv_bfloat16,
                               wmma::col_major> b_h, b_l;
                wmma::load_matrix_sync(b_h, sBh + (wn + j * 16) * STRD + kk, STRD);
                wmma::load_matrix_sync(b_l, sBl + (wn + j * 16) * STRD + kk, STRD);
                wmma::mma_sync(acc[0][j], a_h[0], b_h, acc[0][j]);
                wmma::mma_sync(acc[1][j], a_h[1], b_h, acc[1][j]);
                wmma::mma_sync(acc[0][j], a_h[0], b_l, acc[0][j]);
                wmma::mma_sync(acc[1][j], a_h[1], b_l, acc[1][j]);
                wmma::mma_sync(acc[0][j], a_l[0], b_h, acc[0][j]);
                wmma::mma_sync(acc[1][j], a_l[1], b_h, acc[1][j]);
            }
        }
        if (kc + 1 < NC) CP_WAIT(0);
        __syncthreads();
    }
}

// ---------------------------------------------------------------------------
// Merged KNN-selection + Z-gemm kernel.
//   blockIdx.x <  KNN_CTAS : KNN selection (pair-split, stable top-3)
//   blockIdx.x >= KNN_CTAS : Z = x @ W1_top  tile (fp32 out to g_Z)
// KNN insert is branch-guarded: update needed only when d2 < a2 (strict),
// which is exactly equivalent to the unconditional SEL chain (strict-<
// comparator, later-index ties lose anyway). ~78% of warp-iterations skip.
// ---------------------------------------------------------------------------
#define PTS_PER_BLK 128
#define KNN_CTAS    (NB * NDST / PTS_PER_BLK)   // 256
#define ZG_CTAS     ((MSRC / 128) * (HDIM / 128))  // 128

__global__ __launch_bounds__(256, 2)
void knz_kernel(const float* __restrict__ pos,
                const float* __restrict__ pos_skip,
                const float* __restrict__ x,
                const __nv_bfloat16* __restrict__ Bh,
                const __nv_bfloat16* __restrict__ Bl) {
    extern __shared__ char smem[];
    const int tid = threadIdx.x;

    if (blockIdx.x < KNN_CTAS) {
        // ---------------- KNN selection path ----------------
        float4* spos = (float4*)smem;                 // 32 KB of the 80 KB
        const int bx = blockIdx.x & 63;
        const int b  = blockIdx.x >> 6;

        const float* sp = pos + (size_t)b * NSRC * 3;
        for (int i = tid; i < NSRC; i += 256) {
            float px = sp[i * 3 + 0];
            float py = sp[i * 3 + 1];
            float pz = sp[i * 3 + 2];
            float s2 = __fmaf_rn(pz, pz, __fmaf_rn(py, py, __fmul_rn(px, px)));
            spos[i] = make_float4(px, py, pz, s2);
        }
        __syncthreads();

        const int slot   = tid >> 1;
        const int parity = tid & 1;
        const int m  = b * NDST + bx * PTS_PER_BLK + slot;
        const float dx = pos_skip[m * 3 + 0];
        const float dy = pos_skip[m * 3 + 1];
        const float dz = pos_skip[m * 3 + 2];
        const float dd = __fmaf_rn(dz, dz, __fmaf_rn(dy, dy, __fmul_rn(dx, dx)));

        float a0 = CUDART_INF_F, a1 = CUDART_INF_F, a2 = CUDART_INF_F;
        int   q0 = 0, q1 = 0, q2 = 0;

#pragma unroll 4
        for (int j = parity; j < NSRC; j += 2) {
            float4 c = spos[j];
            float d2 = __fadd_rn(__fadd_rn(dd, c.w),
                       -__fmul_rn(2.0f,
                        __fmaf_rn(dz, c.z, __fmaf_rn(dy, c.y, __fmul_rn(dx, c.x)))));
            if (d2 < a2) {        // rare: exact-equivalent guard (strict <)
                bool p0 = d2 < a0, p1 = d2 < a1;
                q2 = p1 ? q1 : j;
                a2 = p1 ? a1 : d2;
                q1 = p0 ? q0 : (p1 ? j  : q1);
                a1 = p0 ? a0 : (p1 ? d2 : a1);
                q0 = p0 ? j  : q0;
                a0 = p0 ? d2 : a0;
            }
        }

        const unsigned FULL = 0xffffffffu;
        float oa0 = __shfl_down_sync(FULL, a0, 1);
        float oa1 = __shfl_down_sync(FULL, a1, 1);
        float oa2 = __shfl_down_sync(FULL, a2, 1);
        int   oq0 = __shfl_down_sync(FULL, q0, 1);
        int   oq1 = __shfl_down_sync(FULL, q1, 1);
        int   oq2 = __shfl_down_sync(FULL, q2, 1);

        if (parity == 0) {
#pragma unroll
            for (int t = 0; t < 3; ++t) {
                float d  = (t == 0) ? oa0 : (t == 1) ? oa1 : oa2;
                int   jj = (t == 0) ? oq0 : (t == 1) ? oq1 : oq2;
                bool lt0 = (d < a0) || (d == a0 && jj < q0);
                bool lt1 = (d < a1) || (d == a1 && jj < q1);
                bool lt2 = (d < a2) || (d == a2 && jj < q2);
                q2 = lt1 ? q1 : (lt2 ? jj : q2);
                a2 = lt1 ? a1 : (lt2 ? d  : a2);
                q1 = lt0 ? q0 : (lt1 ? jj : q1);
                a1 = lt0 ? a0 : (lt1 ? d  : a1);
                q0 = lt0 ? jj : q0;
                a0 = lt0 ? d  : a0;
            }
            float w0 = __fdiv_rn(1.0f, fmaxf(a0, 1e-16f));
            float w1 = __fdiv_rn(1.0f, fmaxf(a1, 1e-16f));
            float w2 = __fdiv_rn(1.0f, fmaxf(a2, 1e-16f));
            float den = __fadd_rn(__fadd_rn(w0, w1), w2);
            g_selI[m] = make_int4(q0, q1, q2, 0);
            g_selW[m] = make_float4(w0, w1, w2, __fdiv_rn(1.0f, den));
        }
    } else {
        // ---------------- Z-gemm path ----------------
        const int zb = blockIdx.x - KNN_CTAS;
        const uint32_t sbase = (uint32_t)__cvta_generic_to_shared(smem);
        const int w    = tid >> 5;
        const int lane = tid & 31;
        const int bm   = (zb >> 1) * 128;
        const int bn   = (zb & 1) * 128;
        const int wm   = (w & 3) * 32;
        const int wn   = (w >> 2) * 64;

        wmma::fragment<wmma::accumulator, 16, 16, 16, float> acc[2][4];
#pragma unroll
        for (int i = 0; i < 2; ++i)
#pragma unroll
            for (int j = 0; j < 4; ++j)
                wmma::fill_fragment(acc[i][j], 0.0f);

        mma_mainloop_f32A<CIN / BK_G, CIN, CCAT, 0>(
            x, bm, Bh, Bl, bn, smem, sbase, tid, wm, wn, acc);

        float* cw = (float*)smem + w * (32 * CSTR);
#pragma unroll
        for (int i = 0; i < 2; ++i)
#pragma unroll
            for (int j = 0; j < 4; ++j)
                wmma::store_matrix_sync(cw + i * 16 * CSTR + j * 16, acc[i][j],
                                        CSTR, wmma::mem_row_major);
        __syncwarp();

        const int m = bm + wm + lane;
        float4* dst = (float4*)(g_Z + (size_t)m * HDIM + bn + wn);
#pragma unroll
        for (int c = 0; c < 64; c += 4) {
            float4 o;
            o.x = cw[lane * CSTR + c];
            o.y = cw[lane * CSTR + c + 1];
            o.z = cw[lane * CSTR + c + 2];
            o.w = cw[lane * CSTR + c + 3];
            dst[c >> 2] = o;
        }
    }
}

// ---------------------------------------------------------------------------
// S-gemm: S = x_skip @ W1_bot  (M=32768, N=256, K=128), epilogue:
//   h1 = relu( interp(Z) + S + b1 )  -> split bf16 planes
// ---------------------------------------------------------------------------
__global__ __launch_bounds__(256, 2)
void sgemm1_kernel(const float* __restrict__ x_skip,
                   const __nv_bfloat16* __restrict__ Bh,
                   const __nv_bfloat16* __restrict__ Bl,
                   const float* __restrict__ bias) {
    extern __shared__ char smem[];
    __shared__ int4   ssel[128];
    __shared__ float4 swgt[128];
    const uint32_t sbase = (uint32_t)__cvta_generic_to_shared(smem);
    const int tid  = threadIdx.x;
    const int w    = tid >> 5;
    const int lane = tid & 31;
    const int bm   = blockIdx.y * 128;
    const int bn   = blockIdx.x * 128;
    const int wm   = (w & 3) * 32;
    const int wn   = (w >> 2) * 64;
    const int batch = bm >> 13;
    const size_t zbase = (size_t)batch * NSRC;

    if (tid < 128) {
        ssel[tid] = g_selI[bm + tid];
        swgt[tid] = g_selW[bm + tid];
    }

    wmma::fragment<wmma::accumulator, 16, 16, 16, float> acc[2][4];
#pragma unroll
    for (int i = 0; i < 2; ++i)
#pragma unroll
        for (int j = 0; j < 4; ++j)
            wmma::fill_fragment(acc[i][j], 0.0f);

    mma_mainloop_f32A<CSKIP / BK_G, CSKIP, CCAT, CIN>(
        x_skip, bm, Bh, Bl, bn, smem, sbase, tid, wm, wn, acc);

    float* cw = (float*)smem + w * (32 * CSTR);
#pragma unroll
    for (int i = 0; i < 2; ++i)
#pragma unroll
        for (int j = 0; j < 4; ++j)
            wmma::store_matrix_sync(cw + i * 16 * CSTR + j * 16, acc[i][j],
                                    CSTR, wmma::mem_row_major);
    __syncwarp();

    const int ncol0 = bn + wn;
    const float2 bias2 = *(const float2*)(bias + ncol0 + 2 * lane);
#pragma unroll 8
    for (int r = 0; r < 32; ++r) {
        const int row = wm + r;
        const int m   = bm + row;
        const int4   si = ssel[row];
        const float4 sw = swgt[row];
        const float2 z0 = *(const float2*)(g_Z + (zbase + si.x) * HDIM + ncol0 + 2 * lane);
        const float2 z1 = *(const float2*)(g_Z + (zbase + si.y) * HDIM + ncol0 + 2 * lane);
        const float2 z2 = *(const float2*)(g_Z + (zbase + si.z) * HDIM + ncol0 + 2 * lane);
        const float2 s  = *(const float2*)(cw + r * CSTR + 2 * lane);
        float vx = fmaf(sw.x, z0.x, fmaf(sw.y, z1.x, sw.z * z2.x)) * sw.w + s.x + bias2.x;
        float vy = fmaf(sw.x, z0.y, fmaf(sw.y, z1.y, sw.z * z2.y)) * sw.w + s.y + bias2.y;
        vx = fmaxf(vx, 0.0f);
        vy = fmaxf(vy, 0.0f);
        uint16_t h0, l0, h1, l1;
        split_bf16(vx, h0, l0);
        split_bf16(vy, h1, l1);
        uint32_t* dh = (uint32_t*)(g_h1_hi + (size_t)m * HDIM + ncol0);
        uint32_t* dl = (uint32_t*)(g_h1_lo + (size_t)m * HDIM + ncol0);
        dh[lane] = (uint32_t)h0 | ((uint32_t)h1 << 16);
        dl[lane] = (uint32_t)l0 | ((uint32_t)l1 << 16);
    }
}

// ---------------------------------------------------------------------------
// GEMM2 (unchanged): out = (h1 @ W2 + b2) * gate[batch]
// ---------------------------------------------------------------------------
__global__ __launch_bounds__(256, 2)
void gemm2_kernel(const __nv_bfloat16* __restrict__ Ah,
                  const __nv_bfloat16* __restrict__ Al,
                  const __nv_bfloat16* __restrict__ Bh,
                  const __nv_bfloat16* __restrict__ Bl,
                  const float* __restrict__ bias,
                  float* __restrict__ outp) {
    constexpr int KTOT = HDIM;
    constexpr int N    = COUT;
    constexpr int NC   = KTOT / BK_G;      // 8
    extern __shared__ char smem[];
    const uint32_t sbase = (uint32_t)__cvta_generic_to_shared(smem);

    const int tid  = threadIdx.x;
    const int w    = tid >> 5;
    const int lane = tid & 31;
    const int bm   = blockIdx.y * 128;
    const int bn   = blockIdx.x * 128;
    const int wm   = (w & 3) * 32;
    const int wn   = (w >> 2) * 64;

    auto stage = [&](int kc, int buf) {
#pragma unroll
        for (int u = tid; u < 2048; u += 256) {
            const int plane = u >> 9;
            const int idx   = u & 511;
            const int row   = idx >> 2;
            const int c     = idx & 3;
            const __nv_bfloat16* P =
                (plane == 0) ? Ah : (plane == 1) ? Al : (plane == 2) ? Bh : Bl;
            const int grow = (plane < 2) ? (bm + row) : (bn + row);
            const __nv_bfloat16* gsrc =
                P + (size_t)grow * KTOT + kc * BK_G + c * 8;
            uint32_t sdst = sbase + buf * BUF_B + plane * PL_B +
                            row * (STRD * 2) + c * 16;
            cp_async16(sdst, gsrc);
        }
    };

    wmma::fragment<wmma::accumulator, 16, 16, 16, float> acc[2][4];
#pragma unroll
    for (int i = 0; i < 2; ++i)
#pragma unroll
        for (int j = 0; j < 4; ++j)
            wmma::fill_fragment(acc[i][j], 0.0f);

    stage(0, 0);
    CP_COMMIT();

    for (int kc = 0; kc < NC; ++kc) {
        if (kc + 1 < NC) {
            stage(kc + 1, (kc + 1) & 1);
            CP_COMMIT();
            CP_WAIT(1);
        } else {
            CP_WAIT(0);
        }
        __syncthreads();

        const __nv_bfloat16* sb =
            (const __nv_bfloat16*)(smem + (kc & 1) * BUF_B);
        const __nv_bfloat16* sAh = sb;
        const __nv_bfloat16* sAl = sb + 128 * STRD;
        const __nv_bfloat16* sBh = sb + 2 * 128 * STRD;
        const __nv_bfloat16* sBl = sb + 3 * 128 * STRD;

#pragma unroll
        for (int kk = 0; kk < BK_G; kk += 16) {
            wmma::fragment<wmma::matrix_a, 16, 16, 16, __nv_bfloat16,
                           wmma::row_major> a_h[2], a_l[2];
#pragma unroll
            for (int i = 0; i < 2; ++i) {
                wmma::load_matrix_sync(a_h[i], sAh + (wm + i * 16) * STRD + kk, STRD);
                wmma::load_matrix_sync(a_l[i], sAl + (wm + i * 16) * STRD + kk, STRD);
            }
#pragma unroll
            for (int j = 0; j < 4; ++j) {
                wmma::fragment<wmma::matrix_b, 16, 16, 16, __nv_bfloat16,
                               wmma::col_major> b_h, b_l;
                wmma::load_matrix_sync(b_h, sBh + (wn + j * 16) * STRD + kk, STRD);
                wmma::load_matrix_sync(b_l, sBl + (wn + j * 16) * STRD + kk, STRD);
                wmma::mma_sync(acc[0][j], a_h[0], b_h, acc[0][j]);
                wmma::mma_sync(acc[1][j], a_h[1], b_h, acc[1][j]);
                wmma::mma_sync(acc[0][j], a_h[0], b_l, acc[0][j]);
                wmma::mma_sync(acc[1][j], a_h[1], b_l, acc[1][j]);
                wmma::mma_sync(acc[0][j], a_l[0], b_h, acc[0][j]);
                wmma::mma_sync(acc[1][j], a_l[1], b_h, acc[1][j]);
            }
        }
        __syncthreads();
    }

    float* cw = (float*)smem + w * (32 * CSTR);
#pragma unroll
    for (int i = 0; i < 2; ++i)
#pragma unroll
        for (int j = 0; j < 4; ++j)
            wmma::store_matrix_sync(cw + i * 16 * CSTR + j * 16, acc[i][j],
                                    CSTR, wmma::mem_row_major);
    __syncwarp();

    const int m = bm + wm + lane;
    const int ncol0 = bn + wn;
    const int batch = m >> 13;
    const float* gt = g_gate + batch * COUT;
    float4* dst = (float4*)(outp + (size_t)m * N + ncol0);
#pragma unroll
    for (int c = 0; c < 64; c += 4) {
        float4 o;
        o.x = (cw[lane * CSTR + c]     + bias[ncol0 + c])     * gt[ncol0 + c];
        o.y = (cw[lane * CSTR + c + 1] + bias[ncol0 + c + 1]) * gt[ncol0 + c + 1];
        o.z = (cw[lane * CSTR + c + 2] + bias[ncol0 + c + 2]) * gt[ncol0 + c + 2];
        o.w = (cw[lane * CSTR + c + 3] + bias[ncol0 + c + 3]) * gt[ncol0 + c + 3];
        dst[c >> 2] = o;
    }
}

// ---------------------------------------------------------------------------
extern "C" void kernel_launch(void* const* d_in, const int* in_sizes, int n_in,
                              void* d_out, int out_size) {
    const float* par      = (const float*)d_in[0];
    const float* x        = (const float*)d_in[1];
    const float* pos      = (const float*)d_in[2];
    const float* x_skip   = (const float*)d_in[3];
    const float* pos_skip = (const float*)d_in[4];
    const float* W1       = (const float*)d_in[5];
    const float* b1       = (const float*)d_in[6];
    const float* W2       = (const float*)d_in[7];
    const float* b2       = (const float*)d_in[8];
    const float* Wp       = (const float*)d_in[9];
    const float* bp       = (const float*)d_in[10];
    float* out = (float*)d_out;

    __nv_bfloat16 *p_hh, *p_hl, *p_w1h, *p_w1l, *p_w2h, *p_w2l;
    cudaGetSymbolAddress((void**)&p_hh,  g_h1_hi);
    cudaGetSymbolAddress((void**)&p_hl,  g_h1_lo);
    cudaGetSymbolAddress((void**)&p_w1h, g_w1t_hi);
    cudaGetSymbolAddress((void**)&p_w1l, g_w1t_lo);
    cudaGetSymbolAddress((void**)&p_w2h, g_w2t_hi);
    cudaGetSymbolAddress((void**)&p_w2l, g_w2t_lo);

    constexpr int SMEM_G = 2 * BUF_B;   // 81920
    cudaFuncSetAttribute(knz_kernel,
                         cudaFuncAttributeMaxDynamicSharedMemorySize, SMEM_G);
    cudaFuncSetAttribute(sgemm1_kernel,
                         cudaFuncAttributeMaxDynamicSharedMemorySize, SMEM_G);
    cudaFuncSetAttribute(gemm2_kernel,
                         cudaFuncAttributeMaxDynamicSharedMemorySize, SMEM_G);

    const int tail = out_size - OUT_ELEMS;
    int mode = 0;
    if (tail >= POS_ELEMS + 2 * MTOT)      mode = 2;
    else if (tail >= POS_ELEMS + MTOT)     mode = 1;

    prep_kernel<<<(POS_ELEMS + 255) / 256, 256>>>(par, Wp, bp, W1, W2,
                                                  pos_skip, out, mode, out_size);

    knz_kernel<<<KNN_CTAS + ZG_CTAS, 256, SMEM_G>>>(pos, pos_skip, x,
                                                    p_w1h, p_w1l);

    dim3 gs(HDIM / 128, MTOT / 128);       // (2, 256)
    sgemm1_kernel<<<gs, 256, SMEM_G>>>(x_skip, p_w1h, p_w1l, b1);

    dim3 g2(COUT / 128, MTOT / 128);       // (1, 256)
    gemm2_kernel<<<g2, 256, SMEM_G>>>(p_hh, p_hl, p_w2h, p_w2l, b2, out);
}